// round 14
// baseline (speedup 1.0000x reference)
#include <cuda_runtime.h>
#include <cuda_fp16.h>
#include <math.h>
#include <stdint.h>

#define Bc   4
#define Nc   4096
#define Kc   20
#define BN   (Bc*Nc)          // 16384
#define VEPS 1e-6f
#define BNEPS 1e-5f

// ---------------- persistent device scratch (no allocations allowed) -------
__device__ int    g_idx[Bc*Nc*Kc];
__device__ __half g_hAh[BN*4*64], g_hAl[BN*4*64];   // 64-ch h buffers (hi/lo)
__device__ __half g_hBh[BN*4*64], g_hBl[BN*4*64];
__device__ __half g_h16[BN*4*128];                  // fp16 h4 for conv5
__device__ float  g_p[BN*3*128];
__device__ float  g_d[BN*3*128];
__device__ double g_s1[128];
__device__ double g_s2[128];
__device__ double g_s3[128];
__device__ double g_s4[256];
__device__ double g_s5[2048];
__device__ float  g_sumv [Bc*1024*3];
__device__ float  g_sumvn[Bc*1024*3];
// pre-split weights
__device__ __half g_wd2h[128*64], g_wd2l[128*64];   // [W2;D2]
__device__ __half g_wd3h[128*64], g_wd3l[128*64];   // [W3;D3]
__device__ __half g_wd4h[256*64], g_wd4l[256*64];   // [W4;D4]
__device__ __half g_w5h[1024*128], g_w5l[1024*128];

// --------------------------- prep: zero stats + split weights ---------------
__global__ void prep_kernel(const float* __restrict__ W2, const float* __restrict__ D2,
                            const float* __restrict__ W3, const float* __restrict__ D3,
                            const float* __restrict__ W4, const float* __restrict__ D4,
                            const float* __restrict__ W5) {
    int i = blockIdx.x * 256 + threadIdx.x;          // grid 512*256 = 131072
    if (i < 128) { g_s1[i] = 0.0; g_s2[i] = 0.0; g_s3[i] = 0.0; }
    if (i < 256) { g_s4[i] = 0.0; }
    if (i < 2048){ g_s5[i] = 0.0; }
    if (i < Bc*1024*3) { g_sumv[i] = 0.f; g_sumvn[i] = 0.f; }
    {
        float v = W5[i];
        __half h = __float2half_rn(v);
        g_w5h[i] = h;
        g_w5l[i] = __float2half_rn(v - __half2float(h));
    }
    if (i < 16384) {
        int row = i >> 6, col = i & 63;
        float v = (row < 128) ? W4[row*64 + col] : D4[(row-128)*64 + col];
        __half h = __float2half_rn(v);
        g_wd4h[i] = h;
        g_wd4l[i] = __float2half_rn(v - __half2float(h));
    }
    if (i < 8192) {
        int row = i >> 6, col = i & 63;
        float v2 = (row < 64) ? W2[row*64 + col] : D2[(row-64)*64 + col];
        __half h2 = __float2half_rn(v2);
        g_wd2h[i] = h2;
        g_wd2l[i] = __float2half_rn(v2 - __half2float(h2));
        float v3 = (row < 64) ? W3[row*64 + col] : D3[(row-64)*64 + col];
        __half h3 = __float2half_rn(v3);
        g_wd3h[i] = h3;
        g_wd3l[i] = __float2half_rn(v3 - __half2float(h3));
    }
}

// ===================== mma/ldmatrix helpers ==================================
__device__ __forceinline__ uint32_t smem_u32(const void* p) {
    uint32_t a;
    asm("{ .reg .u64 t; cvta.to.shared.u64 t, %1; cvt.u32.u64 %0, t; }" : "=r"(a) : "l"(p));
    return a;
}
__device__ __forceinline__ void ldsm4(uint32_t* r, uint32_t addr) {
    asm volatile("ldmatrix.sync.aligned.m8n8.x4.shared.b16 {%0,%1,%2,%3}, [%4];"
        : "=r"(r[0]), "=r"(r[1]), "=r"(r[2]), "=r"(r[3]) : "r"(addr));
}
__device__ __forceinline__ void mma16816(float* c, const uint32_t* a, uint32_t b0, uint32_t b1) {
    asm volatile("mma.sync.aligned.m16n8k16.row.col.f32.f16.f16.f32 "
        "{%0,%1,%2,%3}, {%4,%5,%6,%7}, {%8,%9}, {%0,%1,%2,%3};"
        : "+f"(c[0]), "+f"(c[1]), "+f"(c[2]), "+f"(c[3])
        : "r"(a[0]), "r"(a[1]), "r"(a[2]), "r"(a[3]), "r"(b0), "r"(b1));
}

// --------------------------- KNN: float4 score scan + redux argmax ----------
#define KNN_SMEM (Nc*16)                 // 65536 bytes

__device__ __forceinline__ uint32_t fkey(float f) {
    uint32_t b = __float_as_uint(f);
    return b ^ (uint32_t)(((int32_t)b >> 31) | 0x80000000);
}

__global__ __launch_bounds__(1024) void knn_kernel(const float* __restrict__ x) {
    extern __shared__ float4 pts[];

    const int tid = threadIdx.x;
    const int b = blockIdx.y;
    const float4* xb4 = (const float4*)(x + (size_t)b * Nc * 3);

    {
        float4 v0 = xb4[tid*3 + 0];
        float4 v1 = xb4[tid*3 + 1];
        float4 v2 = xb4[tid*3 + 2];
        int p = tid * 4;
        pts[p+0] = make_float4(v0.x, v0.y, v0.z, -(v0.x*v0.x + v0.y*v0.y + v0.z*v0.z));
        pts[p+1] = make_float4(v0.w, v1.x, v1.y, -(v0.w*v0.w + v1.x*v1.x + v1.y*v1.y));
        pts[p+2] = make_float4(v1.z, v1.w, v2.x, -(v1.z*v1.z + v1.w*v1.w + v2.x*v2.x));
        pts[p+3] = make_float4(v2.y, v2.z, v2.w, -(v2.y*v2.y + v2.z*v2.z + v2.w*v2.w));
    }
    __syncthreads();

    const int w = tid >> 5, lane = tid & 31;
    const int n = blockIdx.x * 32 + w;

    const float4 q = pts[n];
    const float qx2 = 2.f*q.x, qy2 = 2.f*q.y, qz2 = 2.f*q.z;

    uint32_t mk[4]; uint32_t mi4[4];
    uint32_t msk[4] = {0u, 0u, 0u, 0u};

    #pragma unroll
    for (int c = 0; c < 4; c++) {
        float cm = -3.4e38f; int cj = 0;
        #pragma unroll 8
        for (int i = 0; i < 32; i++) {
            int j = lane + ((c*32 + i) << 5);
            float4 a = pts[j];
            float d = fmaf(a.x, qx2, fmaf(a.y, qy2, fmaf(a.z, qz2, a.w)));
            if (d > cm) { cm = d; cj = j; }
        }
        mk[c] = fkey(cm); mi4[c] = (uint32_t)cj;
    }
    uint32_t bk = mk[0], bj = mi4[0];
    #pragma unroll
    for (int c = 1; c < 4; c++)
        if (mk[c] > bk || (mk[c] == bk && mi4[c] < bj)) { bk = mk[c]; bj = mi4[c]; }

    for (int k = 0; k < Kc; k++) {
        uint32_t best = __reduce_max_sync(0xffffffffu, bk);
        uint32_t cand = (bk == best) ? bj : 0xffffffffu;
        uint32_t j = __reduce_min_sync(0xffffffffu, cand);
        if (lane == 0) g_idx[((size_t)b*Nc + n)*Kc + k] = (int)j;
        if (k == Kc - 1) break;

        const int wl = (int)(j & 31);
        const int C  = (int)(j >> 10);
        const int ib = (int)((j >> 5) & 31);
        if (lane == wl) {
            if (C == 0) msk[0] |= 1u << ib;
            else if (C == 1) msk[1] |= 1u << ib;
            else if (C == 2) msk[2] |= 1u << ib;
            else msk[3] |= 1u << ib;
        }
        uint32_t myb = (C == 0) ? msk[0] : (C == 1) ? msk[1]
                     : (C == 2) ? msk[2] : msk[3];
        uint32_t bm = __shfl_sync(0xffffffffu, myb, wl);

        int jj = wl + ((C*32 + lane) << 5);
        float4 a = pts[jj];
        float d = fmaf(a.x, qx2, fmaf(a.y, qy2, fmaf(a.z, qz2, a.w)));
        uint32_t ck = ((bm >> lane) & 1u) ? 0u : fkey(d);
        uint32_t best2 = __reduce_max_sync(0xffffffffu, ck);
        uint32_t cand2 = (ck == best2 && ck != 0u) ? (uint32_t)jj : 0xffffffffu;
        uint32_t j2 = __reduce_min_sync(0xffffffffu, cand2);

        if (lane == wl) {
            if (C == 0)      { mk[0] = best2; mi4[0] = j2; }
            else if (C == 1) { mk[1] = best2; mi4[1] = j2; }
            else if (C == 2) { mk[2] = best2; mi4[2] = j2; }
            else             { mk[3] = best2; mi4[3] = j2; }
            bk = mk[0]; bj = mi4[0];
            #pragma unroll
            for (int c = 1; c < 4; c++)
                if (mk[c] > bk || (mk[c] == bk && mi4[c] < bj)) { bk = mk[c]; bj = mi4[c]; }
        }
    }
}

// --------------------------- block1 (3ch edge feat -> 64) -------------------
__device__ __forceinline__ void build_f(const float* __restrict__ x, int b, int n0,
                                        float f[2][Kc][9]) {
    int t = threadIdx.x;
    if (t < 2*Kc) {
        int ln = t / Kc, k = t % Kc;
        int n = n0 + ln;
        const float* xb = x + (size_t)b * Nc * 3;
        float cx = xb[n*3+0], cy = xb[n*3+1], cz = xb[n*3+2];
        int j = g_idx[((size_t)b*Nc + n)*Kc + k];
        float ax = xb[j*3+0], ay = xb[j*3+1], az = xb[j*3+2];
        f[ln][k][0] = ax - cx; f[ln][k][1] = ay - cy; f[ln][k][2] = az - cz;
        f[ln][k][3] = cx;      f[ln][k][4] = cy;      f[ln][k][5] = cz;
        f[ln][k][6] = ay*cz - az*cy;
        f[ln][k][7] = az*cx - ax*cz;
        f[ln][k][8] = ax*cy - ay*cx;
    }
}

__global__ __launch_bounds__(128) void block1_stats(const float* __restrict__ x,
                                                    const float* __restrict__ W1) {
    int b = blockIdx.y, n0 = blockIdx.x * 2;
    __shared__ float f[2][Kc][9];
    __shared__ float red[2][128];
    build_f(x, b, n0, f);
    __syncthreads();
    int t = threadIdx.x;
    int ln = t >> 6, c = t & 63;
    float w0 = W1[c*3+0], w1 = W1[c*3+1], w2 = W1[c*3+2];
    float sn = 0.f, sn2 = 0.f;
    #pragma unroll
    for (int k = 0; k < Kc; k++) {
        const float* fk = f[ln][k];
        float p0 = w0*fk[0] + w1*fk[3] + w2*fk[6];
        float p1 = w0*fk[1] + w1*fk[4] + w2*fk[7];
        float p2 = w0*fk[2] + w1*fk[5] + w2*fk[8];
        float nr = sqrtf(p0*p0 + p1*p1 + p2*p2) + VEPS;
        sn += nr; sn2 += nr*nr;
    }
    red[ln][c] = sn; red[ln][64 + c] = sn2;
    __syncthreads();
    if (t < 64) {
        atomicAdd(&g_s1[t],      (double)red[0][t]      + (double)red[1][t]);
        atomicAdd(&g_s1[64 + t], (double)red[0][64 + t] + (double)red[1][64 + t]);
    }
}

__global__ __launch_bounds__(128) void block1_apply(const float* __restrict__ x,
                                                    const float* __restrict__ W1,
                                                    const float* __restrict__ D1,
                                                    const float* __restrict__ g1,
                                                    const float* __restrict__ b1) {
    int b = blockIdx.y, n0 = blockIdx.x * 2;
    __shared__ float f[2][Kc][9];
    build_f(x, b, n0, f);
    __syncthreads();
    int t = threadIdx.x;
    int ln = t >> 6, c = t & 63;
    float w0 = W1[c*3+0], w1 = W1[c*3+1], w2 = W1[c*3+2];
    float e0 = D1[c*3+0], e1 = D1[c*3+1], e2 = D1[c*3+2];
    const double cnt = (double)(Bc*Nc*Kc);
    double mud = g_s1[c] / cnt;
    float  mu  = (float)mud;
    float  rs  = rsqrtf((float)(g_s1[64 + c] / cnt - mud*mud) + BNEPS);
    float ga = g1[c], be = b1[c];
    float a0 = 0.f, a1 = 0.f, a2 = 0.f;
    #pragma unroll
    for (int k = 0; k < Kc; k++) {
        const float* fk = f[ln][k];
        float p0 = w0*fk[0] + w1*fk[3] + w2*fk[6];
        float p1 = w0*fk[1] + w1*fk[4] + w2*fk[7];
        float p2 = w0*fk[2] + w1*fk[5] + w2*fk[8];
        float q  = p0*p0 + p1*p1 + p2*p2;
        float inv = rsqrtf(fmaxf(q, 1e-30f));
        float nr = q*inv + VEPS;
        float sc = (ga*(nr - mu)*rs + be) * inv;
        p0 *= sc; p1 *= sc; p2 *= sc;
        float d0 = e0*fk[0] + e1*fk[3] + e2*fk[6];
        float d1 = e0*fk[1] + e1*fk[4] + e2*fk[7];
        float d2 = e0*fk[2] + e1*fk[5] + e2*fk[8];
        float dot = p0*d0 + p1*d1 + p2*d2;
        if (dot < 0.f) {
            float s2 = __fdividef(dot, d0*d0 + d1*d1 + d2*d2 + VEPS);
            p0 -= s2*d0; p1 -= s2*d1; p2 -= s2*d2;
        }
        a0 += p0; a1 += p1; a2 += p2;
    }
    size_t bn = (size_t)b*Nc + n0 + ln;
    const float inv = 1.f / (float)Kc;
    float v[3] = {a0*inv, a1*inv, a2*inv};
    #pragma unroll
    for (int comp = 0; comp < 3; comp++) {
        __half hv = __float2half_rn(v[comp]);
        g_hAh[(bn*4 + comp)*64 + c] = hv;
        g_hAl[(bn*4 + comp)*64 + c] = __float2half_rn(v[comp] - __half2float(hv));
    }
    g_hAh[(bn*4 + 3)*64 + c] = __float2half_rn(0.f);
    g_hAl[(bn*4 + 3)*64 + c] = __float2half_rn(0.f);
}

// --------------------------- layers 2-4: HMMA p/d GEMM + stats --------------
#define L_OFF_AH 0
#define L_OFF_AL 16384
#define L_OFF_BH 32768
#define L_OFF_BL 49152
#define L_OFF_SS 68096                   // after vsm 128*133*4
#define L_SMEM   69632

template<int COUT, int SRC, int WHICH>
__global__ __launch_bounds__(256, 2) void gemm_hmma() {
    extern __shared__ char smem[];
    const uint32_t sb = smem_u32(smem);
    const int tid  = threadIdx.x;
    const int lane = tid & 31, warp = tid >> 5;
    const int grp  = lane >> 2, tig = lane & 3;
    const int warp_m = warp >> 2, warp_n = warp & 3;
    const int m0 = blockIdx.x * 128;
    const int c0 = blockIdx.y * 128;
    const __half* __restrict__ hh = (SRC == 0) ? g_hAh : g_hBh;
    const __half* __restrict__ hl = (SRC == 0) ? g_hAl : g_hBl;
    const __half* __restrict__ wh = (WHICH == 2) ? g_wd2h : (WHICH == 3) ? g_wd3h : g_wd4h;
    const __half* __restrict__ wl = (WHICH == 2) ? g_wd2l : (WHICH == 3) ? g_wd3l : g_wd4l;
    double* sums = (WHICH == 2) ? g_s2 : (WHICH == 3) ? g_s3 : g_s4;

    float* ssum = (float*)(smem + L_OFF_SS);
    ssum[tid] = 0.f;

    #pragma unroll
    for (int i = 0; i < 4; i++) {
        int e = tid + i*256, r = e >> 3, un = e & 7;
        size_t off = (size_t)(m0 + r)*64 + un*8;
        uint32_t sw = r*128 + ((un ^ (r & 7)) << 4);
        *(uint4*)(smem + L_OFF_AH + sw) = *(const uint4*)(hh + off);
        *(uint4*)(smem + L_OFF_AL + sw) = *(const uint4*)(hl + off);
    }
    #pragma unroll
    for (int i = 0; i < 4; i++) {
        int e = tid + i*256, r = e >> 3, un = e & 7;
        size_t off = (size_t)(c0 + r)*64 + un*8;
        uint32_t sw = r*128 + ((un ^ (r & 7)) << 4);
        *(uint4*)(smem + L_OFF_BH + sw) = *(const uint4*)(wh + off);
        *(uint4*)(smem + L_OFF_BL + sw) = *(const uint4*)(wl + off);
    }
    __syncthreads();

    uint32_t RA[4]; int rxa[4];
    const int u_a = (lane >> 4) & 1;
    #pragma unroll
    for (int mt = 0; mt < 4; mt++) {
        int row = warp_m*64 + mt*16 + (lane & 15);
        RA[mt] = sb + L_OFF_AH + row*128;
        rxa[mt] = row & 7;
    }
    uint32_t RB[2]; int rxb[2];
    const int u_b = (lane >> 3) & 1;
    #pragma unroll
    for (int p = 0; p < 2; p++) {
        int ch = warp_n*32 + p*16 + ((lane & 16) >> 1) + (lane & 7);
        RB[p] = sb + L_OFF_BH + ch*128;
        rxb[p] = ch & 7;
    }

    float acc[4][4][4];
    #pragma unroll
    for (int mt = 0; mt < 4; mt++)
        #pragma unroll
        for (int nt = 0; nt < 4; nt++)
            #pragma unroll
            for (int r4 = 0; r4 < 4; r4++) acc[mt][nt][r4] = 0.f;

    #pragma unroll
    for (int ks = 0; ks < 4; ks++) {
        uint32_t ah[4][4], al[4][4], bh[2][4], bl[2][4];
        #pragma unroll
        for (int mt = 0; mt < 4; mt++) {
            uint32_t off = (uint32_t)(((ks*2 + u_a) ^ rxa[mt]) << 4);
            ldsm4(ah[mt], RA[mt] + off);
            ldsm4(al[mt], RA[mt] + 16384 + off);
        }
        #pragma unroll
        for (int p = 0; p < 2; p++) {
            uint32_t off = (uint32_t)(((ks*2 + u_b) ^ rxb[p]) << 4);
            ldsm4(bh[p], RB[p] + off);
            ldsm4(bl[p], RB[p] + 16384 + off);
        }
        #pragma unroll
        for (int mt = 0; mt < 4; mt++)
            #pragma unroll
            for (int nt = 0; nt < 4; nt++) {
                int p = nt >> 1, ix = (nt & 1) * 2;
                mma16816(acc[mt][nt], ah[mt], bh[p][ix], bh[p][ix+1]);
                mma16816(acc[mt][nt], al[mt], bh[p][ix], bh[p][ix+1]);
                mma16816(acc[mt][nt], ah[mt], bl[p][ix], bl[p][ix+1]);
            }
    }
    __syncthreads();

    float* vsm = (float*)smem;
    #pragma unroll
    for (int mt = 0; mt < 4; mt++)
        #pragma unroll
        for (int nt = 0; nt < 4; nt++)
            #pragma unroll
            for (int r4 = 0; r4 < 4; r4++) {
                int row = warp_m*64 + mt*16 + grp + ((r4 & 2) ? 8 : 0);
                int col = warp_n*32 + nt*8 + 2*tig + (r4 & 1);
                vsm[col*133 + row] = acc[mt][nt][r4];
            }
    __syncthreads();

    {
        int c = tid & 127, halfp = tid >> 7;
        int idx = c0 + c;
        bool isP = (idx < COUT);
        int ch = isP ? idx : idx - COUT;
        float* gout = isP ? g_p : g_d;
        float sn = 0.f, sn2 = 0.f;
        const float* vc = vsm + c*133 + halfp*64;
        int bn0 = blockIdx.x*32 + halfp*16;
        #pragma unroll
        for (int i = 0; i < 16; i++) {
            float v0 = vc[i*4 + 0], v1 = vc[i*4 + 1], v2 = vc[i*4 + 2];
            size_t row = (size_t)(bn0 + i) * 3;
            gout[(row + 0)*COUT + ch] = v0;
            gout[(row + 1)*COUT + ch] = v1;
            gout[(row + 2)*COUT + ch] = v2;
            if (isP) {
                float q  = v0*v0 + v1*v1 + v2*v2;
                sn += sqrtf(q) + VEPS; sn2 += q;
            }
        }
        if (isP) {
            atomicAdd(&ssum[ch & 127], sn);
            atomicAdd(&ssum[128 + (ch & 127)], sn2);
        }
    }
    __syncthreads();
    if (c0 == 0 && tid < COUT) {
        atomicAdd(&sums[tid],        (double)ssum[tid & 127]);
        atomicAdd(&sums[COUT + tid], (double)ssum[128 + (tid & 127)]);
    }
}

// --------------------------- apply BN + VN-leaky (inline finalize) ----------
// DST: 0 = g_hA (hi/lo), 1 = g_hB (hi/lo), 2 = g_h16 (fp16 single)
template<int COUT, int DST, int WHICH>
__global__ __launch_bounds__(256) void apply_bn_leaky(const float* __restrict__ ga,
                                                      const float* __restrict__ be) {
    const double* s = (WHICH == 2) ? g_s2 : (WHICH == 3) ? g_s3 : g_s4;
    int i = blockIdx.x * 256 + threadIdx.x;
    if (i >= BN * COUT) return;
    int bn = i / COUT, c = i % COUT;
    const double cnt = (double)BN;
    double mud = s[c] / cnt;
    float  mu  = (float)mud;
    float  rs  = rsqrtf((float)(s[COUT + c] / cnt - mud*mud) + BNEPS);
    size_t r = (size_t)bn * 3;
    float p0 = g_p[(r+0)*COUT + c], p1 = g_p[(r+1)*COUT + c], p2 = g_p[(r+2)*COUT + c];
    float q  = p0*p0 + p1*p1 + p2*p2;
    float inv = rsqrtf(fmaxf(q, 1e-30f));
    float nr = q*inv + VEPS;
    float sc = (ga[c]*(nr - mu)*rs + be[c]) * inv;
    p0 *= sc; p1 *= sc; p2 *= sc;
    float d0 = g_d[(r+0)*COUT + c], d1 = g_d[(r+1)*COUT + c], d2 = g_d[(r+2)*COUT + c];
    float dot = p0*d0 + p1*d1 + p2*d2;
    if (dot < 0.f) {
        float s2 = __fdividef(dot, d0*d0 + d1*d1 + d2*d2 + VEPS);
        p0 -= s2*d0; p1 -= s2*d1; p2 -= s2*d2;
    }
    size_t ro = (size_t)bn * 4;
    if (DST == 2) {
        g_h16[(ro+0)*COUT + c] = __float2half_rn(p0);
        g_h16[(ro+1)*COUT + c] = __float2half_rn(p1);
        g_h16[(ro+2)*COUT + c] = __float2half_rn(p2);
        g_h16[(ro+3)*COUT + c] = __float2half_rn(0.f);
    } else {
        __half* hh = (DST == 0) ? g_hAh : g_hBh;
        __half* hl = (DST == 0) ? g_hAl : g_hBl;
        float v[3] = {p0, p1, p2};
        #pragma unroll
        for (int comp = 0; comp < 3; comp++) {
            __half hv = __float2half_rn(v[comp]);
            hh[(ro+comp)*COUT + c] = hv;
            hl[(ro+comp)*COUT + c] = __float2half_rn(v[comp] - __half2float(hv));
        }
        hh[(ro+3)*COUT + c] = __float2half_rn(0.f);
        hl[(ro+3)*COUT + c] = __float2half_rn(0.f);
    }
}

// --------------------------- conv5: fp16 mma.sync, M=256/block, B reused -----
// 512 threads: warps 0-7 -> m-tile 0, warps 8-15 -> m-tile 1 (shared B tile).
// smem: REG0 [0, 68096) = A0@0 + A1@32768 (mainloop), vsm@0 (epilogue);
//       BH@68096, BL@100864, accf@133632. Total 137728 B, 1 block/SM.
#define C5_OFF_A   0
#define C5_OFF_BH  68096
#define C5_OFF_BL  100864
#define C5_OFF_ACC 133632
#define C5_SMEM    137728

__device__ __forceinline__ int c5_swz(int row, int b8) {   // b8: byte off in 256B row
    return (row << 8) + (b8 ^ (((row & 3) << 5) | ((row & 4) << 2)));
}

__global__ __launch_bounds__(512, 1) void conv5_hmma() {
    extern __shared__ char smem[];
    const uint32_t sb = smem_u32(smem);
    float* accf = (float*)(smem + C5_OFF_ACC);
    float* vsm  = (float*)smem;

    const int tid  = threadIdx.x;
    const int lane = tid & 31, warp = tid >> 5;
    const int grp  = lane >> 2, tig = lane & 3;
    const int g    = warp >> 3;          // m-subtile 0/1
    const int wl8  = warp & 7;
    const int warp_m = wl8 >> 2, warp_n = wl8 & 3;
    const int m0 = blockIdx.x * 256;     // padded row base (64 points)
    const int c0 = blockIdx.y * 128;

    for (int i = tid; i < 1024; i += 512) accf[i] = 0.f;

    // ---- stage 2 A tiles (both by all threads) ----
    #pragma unroll
    for (int i = 0; i < 16; i++) {
        int e = tid + i*512;             // 0..8191
        int tl = e >> 12, r = (e >> 5) & 127, q = e & 31;
        uint2 hv = *(const uint2*)(g_h16 + (size_t)(m0 + tl*128 + r)*128 + q*4);
        *(uint2*)(smem + C5_OFF_A + tl*32768 + c5_swz(r, q*8)) = hv;
    }
    // ---- stage B (shared) ----
    #pragma unroll
    for (int i = 0; i < 8; i++) {
        int e = tid + i*512, r = e >> 5, q = e & 31;
        size_t off = (size_t)(c0 + r)*128 + q*4;
        int sw = c5_swz(r, q*8);
        *(uint2*)(smem + C5_OFF_BH + sw) = *(const uint2*)(g_w5h + off);
        *(uint2*)(smem + C5_OFF_BL + sw) = *(const uint2*)(g_w5l + off);
    }
    __syncthreads();

    uint32_t PA[4], XA[4];
    const uint32_t Abase = sb + C5_OFF_A + g*32768;
    #pragma unroll
    for (int mt = 0; mt < 4; mt++) {
        int row = warp_m*64 + mt*16 + (lane & 15);
        XA[mt] = (row & 3) << 5;
        PA[mt] = Abase + row*256 + ((lane & 16) ^ ((row & 4) << 2));
    }
    uint32_t PBh[2], PBl[2], XB[2];
    #pragma unroll
    for (int p = 0; p < 2; p++) {
        int ch = warp_n*32 + p*16 + ((lane & 16) >> 1) + (lane & 7);
        XB[p]  = (ch & 3) << 5;
        uint32_t off = ch*256 + (((lane & 8) << 1) ^ ((ch & 4) << 2));
        PBh[p] = sb + C5_OFF_BH + off;
        PBl[p] = sb + C5_OFF_BL + off;
    }

    float acc[4][4][4];
    #pragma unroll
    for (int mt = 0; mt < 4; mt++)
        #pragma unroll
        for (int nt = 0; nt < 4; nt++)
            #pragma unroll
            for (int r4 = 0; r4 < 4; r4++) acc[mt][nt][r4] = 0.f;

    #pragma unroll
    for (int ks = 0; ks < 8; ks++) {
        uint32_t a[4][4], bh[2][4], bl[2][4];
        #pragma unroll
        for (int mt = 0; mt < 4; mt++) ldsm4(a[mt], PA[mt] + ((ks*32) ^ XA[mt]));
        #pragma unroll
        for (int p = 0; p < 2; p++) {
            ldsm4(bh[p], PBh[p] + ((ks*32) ^ XB[p]));
            ldsm4(bl[p], PBl[p] + ((ks*32) ^ XB[p]));
        }
        #pragma unroll
        for (int mt = 0; mt < 4; mt++)
            #pragma unroll
            for (int nt = 0; nt < 4; nt++) {
                int p = nt >> 1, ix = (nt & 1) * 2;
                mma16816(acc[mt][nt], a[mt], bh[p][ix], bh[p][ix+1]);
                mma16816(acc[mt][nt], a[mt], bl[p][ix], bl[p][ix+1]);
            }
    }
    __syncthreads();

    // ---- epilogue per m-subtile (vsm reuses A region) ----
    #pragma unroll
    for (int g2 = 0; g2 < 2; g2++) {
        if (g == g2) {
            #pragma unroll
            for (int mt = 0; mt < 4; mt++)
                #pragma unroll
                for (int nt = 0; nt < 4; nt++)
                    #pragma unroll
                    for (int r4 = 0; r4 < 4; r4++) {
                        int row = warp_m*64 + mt*16 + grp + ((r4 & 2) ? 8 : 0);
                        int col = warp_n*32 + nt*8 + 2*tig + (r4 & 1);
                        vsm[col*133 + row] = acc[mt][nt][r4];
                    }
        }
        __syncthreads();
        {
            int c = tid & 127, qtr = tid >> 7;   // 4 threads/col, 8 points each
            float sn = 0.f, sn2 = 0.f;
            float sv0 = 0.f, sv1 = 0.f, sv2 = 0.f;
            float sw0 = 0.f, sw1 = 0.f, sw2 = 0.f;
            const float* vc = vsm + c*133 + qtr*32;
            #pragma unroll
            for (int i = 0; i < 8; i++) {
                float v0 = vc[i*4 + 0], v1 = vc[i*4 + 1], v2 = vc[i*4 + 2];
                float q  = v0*v0 + v1*v1 + v2*v2;
                float inv = rsqrtf(fmaxf(q, 1e-30f));
                float nr = q*inv + VEPS;
                sn += nr; sn2 += q;
                sv0 += v0; sv1 += v1; sv2 += v2;
                sw0 += v0*inv; sw1 += v1*inv; sw2 += v2*inv;
            }
            atomicAdd(&accf[c*8 + 0], sn);
            atomicAdd(&accf[c*8 + 1], sn2);
            atomicAdd(&accf[c*8 + 2], sv0);
            atomicAdd(&accf[c*8 + 3], sv1);
            atomicAdd(&accf[c*8 + 4], sv2);
            atomicAdd(&accf[c*8 + 5], sw0);
            atomicAdd(&accf[c*8 + 6], sw1);
            atomicAdd(&accf[c*8 + 7], sw2);
        }
        __syncthreads();
    }

    const int b = blockIdx.x >> 6;       // 64 points/block, 4096/batch
    for (int i = tid; i < 1024; i += 512) {
        int c = i >> 3, q = i & 7;
        float vv = accf[i];
        int cg = c0 + c;
        if (q == 0)      atomicAdd(&g_s5[cg],        (double)vv);
        else if (q == 1) atomicAdd(&g_s5[1024 + cg], (double)vv);
        else if (q < 5)  atomicAdd(&g_sumv [(b*1024 + cg)*3 + (q-2)], vv);
        else             atomicAdd(&g_sumvn[(b*1024 + cg)*3 + (q-5)], vv);
    }
}

// --------------------------- final output ------------------------------------
__global__ void final_out(const float* __restrict__ g5, const float* __restrict__ b5,
                          float* __restrict__ out) {
    int c = blockIdx.x * 256 + threadIdx.x;
    if (c >= 1024) return;
    double mu  = g_s5[c]        / (double)BN;
    double var = g_s5[1024 + c] / (double)BN - mu*mu;
    float rs  = (float)(1.0 / sqrt(var + (double)BNEPS));
    float a   = g5[c] * rs;
    float t   = a * (float)mu - b5[c];
    #pragma unroll
    for (int b = 0; b < Bc; b++)
        #pragma unroll
        for (int comp = 0; comp < 3; comp++) {
            int gi = (b*1024 + c)*3 + comp;
            out[gi] = a * (g_sumv[gi] * (1.f/(float)Nc))
                    - t * (g_sumvn[gi] * (1.f/(float)Nc));
        }
}

// ---------------------------------------------------------------------------
extern "C" void kernel_launch(void* const* d_in, const int* in_sizes, int n_in,
                              void* d_out, int out_size) {
    const float* x  = (const float*)d_in[0];
    const float* W1 = (const float*)d_in[1];
    const float* D1 = (const float*)d_in[2];
    const float* g1 = (const float*)d_in[3];
    const float* b1 = (const float*)d_in[4];
    const float* W2 = (const float*)d_in[5];
    const float* D2 = (const float*)d_in[6];
    const float* g2 = (const float*)d_in[7];
    const float* b2 = (const float*)d_in[8];
    const float* W3 = (const float*)d_in[9];
    const float* D3 = (const float*)d_in[10];
    const float* g3 = (const float*)d_in[11];
    const float* b3 = (const float*)d_in[12];
    const float* W4 = (const float*)d_in[13];
    const float* D4 = (const float*)d_in[14];
    const float* g4 = (const float*)d_in[15];
    const float* b4 = (const float*)d_in[16];
    const float* W5 = (const float*)d_in[17];
    const float* g5 = (const float*)d_in[18];
    const float* b5 = (const float*)d_in[19];
    float* out = (float*)d_out;

    cudaFuncSetAttribute(knn_kernel, cudaFuncAttributeMaxDynamicSharedMemorySize, KNN_SMEM);
    cudaFuncSetAttribute(conv5_hmma, cudaFuncAttributeMaxDynamicSharedMemorySize, C5_SMEM);
    cudaFuncSetAttribute(gemm_hmma<64, 0, 2>, cudaFuncAttributeMaxDynamicSharedMemorySize, L_SMEM);
    cudaFuncSetAttribute(gemm_hmma<64, 1, 3>, cudaFuncAttributeMaxDynamicSharedMemorySize, L_SMEM);
    cudaFuncSetAttribute(gemm_hmma<128, 0, 4>, cudaFuncAttributeMaxDynamicSharedMemorySize, L_SMEM);

    prep_kernel<<<512, 256>>>(W2, D2, W3, D3, W4, D4, W5);  // my idx 0
    knn_kernel<<<dim3(Nc/32, Bc), 1024, KNN_SMEM>>>(x);     // my idx 1

    block1_stats<<<dim3(Nc/2, Bc), 128>>>(x, W1);           // my idx 2
    block1_apply<<<dim3(Nc/2, Bc), 128>>>(x, W1, D1, g1, b1);  // my idx 3 == profiled

    gemm_hmma<64, 0, 2><<<dim3(512, 1), 256, L_SMEM>>>();
    apply_bn_leaky<64, 1, 2><<<(BN*64 + 255)/256, 256>>>(g2, b2);

    gemm_hmma<64, 1, 3><<<dim3(512, 1), 256, L_SMEM>>>();
    apply_bn_leaky<64, 0, 3><<<(BN*64 + 255)/256, 256>>>(g3, b3);

    gemm_hmma<128, 0, 4><<<dim3(512, 2), 256, L_SMEM>>>();
    apply_bn_leaky<128, 2, 4><<<(BN*128 + 255)/256, 256>>>(g4, b4);

    conv5_hmma<<<dim3(BN*4/256, 1024/128), 512, C5_SMEM>>>();
    final_out<<<4, 256>>>(g5, b5, out);
}

// round 15
// speedup vs baseline: 1.0896x; 1.0896x over previous
#include <cuda_runtime.h>
#include <cuda_fp16.h>
#include <math.h>
#include <stdint.h>

#define Bc   4
#define Nc   4096
#define Kc   20
#define BN   (Bc*Nc)          // 16384
#define VEPS 1e-6f
#define BNEPS 1e-5f

// ---------------- persistent device scratch (no allocations allowed) -------
__device__ int    g_idx[Bc*Nc*Kc];
__device__ __half g_hAh[BN*4*64], g_hAl[BN*4*64];   // 64-ch h buffers (hi/lo)
__device__ __half g_hBh[BN*4*64], g_hBl[BN*4*64];
__device__ __half g_h16[BN*4*128];                  // fp16 h4 for conv5
__device__ float  g_p[BN*3*128];
__device__ float  g_d[BN*3*128];
__device__ double g_s1[128];
__device__ double g_s2[128];
__device__ double g_s3[128];
__device__ double g_s4[256];
__device__ double g_s5[2048];
__device__ float  g_sumv [Bc*1024*3];
__device__ float  g_sumvn[Bc*1024*3];
// pre-split weights
__device__ __half g_wd2h[128*64], g_wd2l[128*64];   // [W2;D2]
__device__ __half g_wd3h[128*64], g_wd3l[128*64];   // [W3;D3]
__device__ __half g_wd4h[256*64], g_wd4l[256*64];   // [W4;D4]
__device__ __half g_w5h[1024*128], g_w5l[1024*128];

// --------------------------- prep: zero stats + split weights ---------------
__global__ void prep_kernel(const float* __restrict__ W2, const float* __restrict__ D2,
                            const float* __restrict__ W3, const float* __restrict__ D3,
                            const float* __restrict__ W4, const float* __restrict__ D4,
                            const float* __restrict__ W5) {
    int i = blockIdx.x * 256 + threadIdx.x;          // grid 512*256 = 131072
    if (i < 128) { g_s1[i] = 0.0; g_s2[i] = 0.0; g_s3[i] = 0.0; }
    if (i < 256) { g_s4[i] = 0.0; }
    if (i < 2048){ g_s5[i] = 0.0; }
    if (i < Bc*1024*3) { g_sumv[i] = 0.f; g_sumvn[i] = 0.f; }
    {
        float v = W5[i];
        __half h = __float2half_rn(v);
        g_w5h[i] = h;
        g_w5l[i] = __float2half_rn(v - __half2float(h));
    }
    if (i < 16384) {
        int row = i >> 6, col = i & 63;
        float v = (row < 128) ? W4[row*64 + col] : D4[(row-128)*64 + col];
        __half h = __float2half_rn(v);
        g_wd4h[i] = h;
        g_wd4l[i] = __float2half_rn(v - __half2float(h));
    }
    if (i < 8192) {
        int row = i >> 6, col = i & 63;
        float v2 = (row < 64) ? W2[row*64 + col] : D2[(row-64)*64 + col];
        __half h2 = __float2half_rn(v2);
        g_wd2h[i] = h2;
        g_wd2l[i] = __float2half_rn(v2 - __half2float(h2));
        float v3 = (row < 64) ? W3[row*64 + col] : D3[(row-64)*64 + col];
        __half h3 = __float2half_rn(v3);
        g_wd3h[i] = h3;
        g_wd3l[i] = __float2half_rn(v3 - __half2float(h3));
    }
}

// ===================== mma/ldmatrix helpers ==================================
__device__ __forceinline__ uint32_t smem_u32(const void* p) {
    uint32_t a;
    asm("{ .reg .u64 t; cvta.to.shared.u64 t, %1; cvt.u32.u64 %0, t; }" : "=r"(a) : "l"(p));
    return a;
}
__device__ __forceinline__ void ldsm4(uint32_t* r, uint32_t addr) {
    asm volatile("ldmatrix.sync.aligned.m8n8.x4.shared.b16 {%0,%1,%2,%3}, [%4];"
        : "=r"(r[0]), "=r"(r[1]), "=r"(r[2]), "=r"(r[3]) : "r"(addr));
}
__device__ __forceinline__ void mma16816(float* c, const uint32_t* a, uint32_t b0, uint32_t b1) {
    asm volatile("mma.sync.aligned.m16n8k16.row.col.f32.f16.f16.f32 "
        "{%0,%1,%2,%3}, {%4,%5,%6,%7}, {%8,%9}, {%0,%1,%2,%3};"
        : "+f"(c[0]), "+f"(c[1]), "+f"(c[2]), "+f"(c[3])
        : "r"(a[0]), "r"(a[1]), "r"(a[2]), "r"(a[3]), "r"(b0), "r"(b1));
}

// --------------------------- KNN: float4 score scan + redux argmax ----------
#define KNN_SMEM (Nc*16)                 // 65536 bytes

__device__ __forceinline__ uint32_t fkey(float f) {
    uint32_t b = __float_as_uint(f);
    return b ^ (uint32_t)(((int32_t)b >> 31) | 0x80000000);
}

__global__ __launch_bounds__(1024) void knn_kernel(const float* __restrict__ x) {
    extern __shared__ float4 pts[];

    const int tid = threadIdx.x;
    const int b = blockIdx.y;
    const float4* xb4 = (const float4*)(x + (size_t)b * Nc * 3);

    {
        float4 v0 = xb4[tid*3 + 0];
        float4 v1 = xb4[tid*3 + 1];
        float4 v2 = xb4[tid*3 + 2];
        int p = tid * 4;
        pts[p+0] = make_float4(v0.x, v0.y, v0.z, -(v0.x*v0.x + v0.y*v0.y + v0.z*v0.z));
        pts[p+1] = make_float4(v0.w, v1.x, v1.y, -(v0.w*v0.w + v1.x*v1.x + v1.y*v1.y));
        pts[p+2] = make_float4(v1.z, v1.w, v2.x, -(v1.z*v1.z + v1.w*v1.w + v2.x*v2.x));
        pts[p+3] = make_float4(v2.y, v2.z, v2.w, -(v2.y*v2.y + v2.z*v2.z + v2.w*v2.w));
    }
    __syncthreads();

    const int w = tid >> 5, lane = tid & 31;
    const int n = blockIdx.x * 32 + w;

    const float4 q = pts[n];
    const float qx2 = 2.f*q.x, qy2 = 2.f*q.y, qz2 = 2.f*q.z;

    uint32_t mk[4]; uint32_t mi4[4];
    uint32_t msk[4] = {0u, 0u, 0u, 0u};

    #pragma unroll
    for (int c = 0; c < 4; c++) {
        float cm = -3.4e38f; int cj = 0;
        #pragma unroll 8
        for (int i = 0; i < 32; i++) {
            int j = lane + ((c*32 + i) << 5);
            float4 a = pts[j];
            float d = fmaf(a.x, qx2, fmaf(a.y, qy2, fmaf(a.z, qz2, a.w)));
            if (d > cm) { cm = d; cj = j; }
        }
        mk[c] = fkey(cm); mi4[c] = (uint32_t)cj;
    }
    uint32_t bk = mk[0], bj = mi4[0];
    #pragma unroll
    for (int c = 1; c < 4; c++)
        if (mk[c] > bk || (mk[c] == bk && mi4[c] < bj)) { bk = mk[c]; bj = mi4[c]; }

    for (int k = 0; k < Kc; k++) {
        uint32_t best = __reduce_max_sync(0xffffffffu, bk);
        uint32_t cand = (bk == best) ? bj : 0xffffffffu;
        uint32_t j = __reduce_min_sync(0xffffffffu, cand);
        if (lane == 0) g_idx[((size_t)b*Nc + n)*Kc + k] = (int)j;
        if (k == Kc - 1) break;

        const int wl = (int)(j & 31);
        const int C  = (int)(j >> 10);
        const int ib = (int)((j >> 5) & 31);
        if (lane == wl) {
            if (C == 0) msk[0] |= 1u << ib;
            else if (C == 1) msk[1] |= 1u << ib;
            else if (C == 2) msk[2] |= 1u << ib;
            else msk[3] |= 1u << ib;
        }
        uint32_t myb = (C == 0) ? msk[0] : (C == 1) ? msk[1]
                     : (C == 2) ? msk[2] : msk[3];
        uint32_t bm = __shfl_sync(0xffffffffu, myb, wl);

        int jj = wl + ((C*32 + lane) << 5);
        float4 a = pts[jj];
        float d = fmaf(a.x, qx2, fmaf(a.y, qy2, fmaf(a.z, qz2, a.w)));
        uint32_t ck = ((bm >> lane) & 1u) ? 0u : fkey(d);
        uint32_t best2 = __reduce_max_sync(0xffffffffu, ck);
        uint32_t cand2 = (ck == best2 && ck != 0u) ? (uint32_t)jj : 0xffffffffu;
        uint32_t j2 = __reduce_min_sync(0xffffffffu, cand2);

        if (lane == wl) {
            if (C == 0)      { mk[0] = best2; mi4[0] = j2; }
            else if (C == 1) { mk[1] = best2; mi4[1] = j2; }
            else if (C == 2) { mk[2] = best2; mi4[2] = j2; }
            else             { mk[3] = best2; mi4[3] = j2; }
            bk = mk[0]; bj = mi4[0];
            #pragma unroll
            for (int c = 1; c < 4; c++)
                if (mk[c] > bk || (mk[c] == bk && mi4[c] < bj)) { bk = mk[c]; bj = mi4[c]; }
        }
    }
}

// --------------------------- block1 (3ch edge feat -> 64) -------------------
__device__ __forceinline__ void build_f(const float* __restrict__ x, int b, int n0,
                                        float f[2][Kc][9]) {
    int t = threadIdx.x;
    if (t < 2*Kc) {
        int ln = t / Kc, k = t % Kc;
        int n = n0 + ln;
        const float* xb = x + (size_t)b * Nc * 3;
        float cx = xb[n*3+0], cy = xb[n*3+1], cz = xb[n*3+2];
        int j = g_idx[((size_t)b*Nc + n)*Kc + k];
        float ax = xb[j*3+0], ay = xb[j*3+1], az = xb[j*3+2];
        f[ln][k][0] = ax - cx; f[ln][k][1] = ay - cy; f[ln][k][2] = az - cz;
        f[ln][k][3] = cx;      f[ln][k][4] = cy;      f[ln][k][5] = cz;
        f[ln][k][6] = ay*cz - az*cy;
        f[ln][k][7] = az*cx - ax*cz;
        f[ln][k][8] = ax*cy - ay*cx;
    }
}

__global__ __launch_bounds__(128) void block1_stats(const float* __restrict__ x,
                                                    const float* __restrict__ W1) {
    int b = blockIdx.y, n0 = blockIdx.x * 2;
    __shared__ float f[2][Kc][9];
    __shared__ float red[2][128];
    build_f(x, b, n0, f);
    __syncthreads();
    int t = threadIdx.x;
    int ln = t >> 6, c = t & 63;
    float w0 = W1[c*3+0], w1 = W1[c*3+1], w2 = W1[c*3+2];
    float sn = 0.f, sn2 = 0.f;
    #pragma unroll
    for (int k = 0; k < Kc; k++) {
        const float* fk = f[ln][k];
        float p0 = w0*fk[0] + w1*fk[3] + w2*fk[6];
        float p1 = w0*fk[1] + w1*fk[4] + w2*fk[7];
        float p2 = w0*fk[2] + w1*fk[5] + w2*fk[8];
        float nr = sqrtf(p0*p0 + p1*p1 + p2*p2) + VEPS;
        sn += nr; sn2 += nr*nr;
    }
    red[ln][c] = sn; red[ln][64 + c] = sn2;
    __syncthreads();
    if (t < 64) {
        atomicAdd(&g_s1[t],      (double)red[0][t]      + (double)red[1][t]);
        atomicAdd(&g_s1[64 + t], (double)red[0][64 + t] + (double)red[1][64 + t]);
    }
}

__global__ __launch_bounds__(128) void block1_apply(const float* __restrict__ x,
                                                    const float* __restrict__ W1,
                                                    const float* __restrict__ D1,
                                                    const float* __restrict__ g1,
                                                    const float* __restrict__ b1) {
    int b = blockIdx.y, n0 = blockIdx.x * 2;
    __shared__ float f[2][Kc][9];
    build_f(x, b, n0, f);
    __syncthreads();
    int t = threadIdx.x;
    int ln = t >> 6, c = t & 63;
    float w0 = W1[c*3+0], w1 = W1[c*3+1], w2 = W1[c*3+2];
    float e0 = D1[c*3+0], e1 = D1[c*3+1], e2 = D1[c*3+2];
    const double cnt = (double)(Bc*Nc*Kc);
    double mud = g_s1[c] / cnt;
    float  mu  = (float)mud;
    float  rs  = rsqrtf((float)(g_s1[64 + c] / cnt - mud*mud) + BNEPS);
    float ga = g1[c], be = b1[c];
    float a0 = 0.f, a1 = 0.f, a2 = 0.f;
    #pragma unroll
    for (int k = 0; k < Kc; k++) {
        const float* fk = f[ln][k];
        float p0 = w0*fk[0] + w1*fk[3] + w2*fk[6];
        float p1 = w0*fk[1] + w1*fk[4] + w2*fk[7];
        float p2 = w0*fk[2] + w1*fk[5] + w2*fk[8];
        float q  = p0*p0 + p1*p1 + p2*p2;
        float inv = rsqrtf(fmaxf(q, 1e-30f));
        float nr = q*inv + VEPS;
        float sc = (ga*(nr - mu)*rs + be) * inv;
        p0 *= sc; p1 *= sc; p2 *= sc;
        float d0 = e0*fk[0] + e1*fk[3] + e2*fk[6];
        float d1 = e0*fk[1] + e1*fk[4] + e2*fk[7];
        float d2 = e0*fk[2] + e1*fk[5] + e2*fk[8];
        float dot = p0*d0 + p1*d1 + p2*d2;
        if (dot < 0.f) {
            float s2 = __fdividef(dot, d0*d0 + d1*d1 + d2*d2 + VEPS);
            p0 -= s2*d0; p1 -= s2*d1; p2 -= s2*d2;
        }
        a0 += p0; a1 += p1; a2 += p2;
    }
    size_t bn = (size_t)b*Nc + n0 + ln;
    const float inv = 1.f / (float)Kc;
    float v[3] = {a0*inv, a1*inv, a2*inv};
    #pragma unroll
    for (int comp = 0; comp < 3; comp++) {
        __half hv = __float2half_rn(v[comp]);
        g_hAh[(bn*4 + comp)*64 + c] = hv;
        g_hAl[(bn*4 + comp)*64 + c] = __float2half_rn(v[comp] - __half2float(hv));
    }
    g_hAh[(bn*4 + 3)*64 + c] = __float2half_rn(0.f);
    g_hAl[(bn*4 + 3)*64 + c] = __float2half_rn(0.f);
}

// --------------------------- layers 2-4: HMMA p/d GEMM + stats --------------
#define L_OFF_AH 0
#define L_OFF_AL 16384
#define L_OFF_BH 32768
#define L_OFF_BL 49152
#define L_OFF_SS 68096                   // after vsm 128*133*4
#define L_SMEM   69632

template<int COUT, int SRC, int WHICH>
__global__ __launch_bounds__(256, 2) void gemm_hmma() {
    extern __shared__ char smem[];
    const uint32_t sb = smem_u32(smem);
    const int tid  = threadIdx.x;
    const int lane = tid & 31, warp = tid >> 5;
    const int grp  = lane >> 2, tig = lane & 3;
    const int warp_m = warp >> 2, warp_n = warp & 3;
    const int m0 = blockIdx.x * 128;
    const int c0 = blockIdx.y * 128;
    const __half* __restrict__ hh = (SRC == 0) ? g_hAh : g_hBh;
    const __half* __restrict__ hl = (SRC == 0) ? g_hAl : g_hBl;
    const __half* __restrict__ wh = (WHICH == 2) ? g_wd2h : (WHICH == 3) ? g_wd3h : g_wd4h;
    const __half* __restrict__ wl = (WHICH == 2) ? g_wd2l : (WHICH == 3) ? g_wd3l : g_wd4l;
    double* sums = (WHICH == 2) ? g_s2 : (WHICH == 3) ? g_s3 : g_s4;

    float* ssum = (float*)(smem + L_OFF_SS);
    ssum[tid] = 0.f;

    #pragma unroll
    for (int i = 0; i < 4; i++) {
        int e = tid + i*256, r = e >> 3, un = e & 7;
        size_t off = (size_t)(m0 + r)*64 + un*8;
        uint32_t sw = r*128 + ((un ^ (r & 7)) << 4);
        *(uint4*)(smem + L_OFF_AH + sw) = *(const uint4*)(hh + off);
        *(uint4*)(smem + L_OFF_AL + sw) = *(const uint4*)(hl + off);
    }
    #pragma unroll
    for (int i = 0; i < 4; i++) {
        int e = tid + i*256, r = e >> 3, un = e & 7;
        size_t off = (size_t)(c0 + r)*64 + un*8;
        uint32_t sw = r*128 + ((un ^ (r & 7)) << 4);
        *(uint4*)(smem + L_OFF_BH + sw) = *(const uint4*)(wh + off);
        *(uint4*)(smem + L_OFF_BL + sw) = *(const uint4*)(wl + off);
    }
    __syncthreads();

    uint32_t RA[4]; int rxa[4];
    const int u_a = (lane >> 4) & 1;
    #pragma unroll
    for (int mt = 0; mt < 4; mt++) {
        int row = warp_m*64 + mt*16 + (lane & 15);
        RA[mt] = sb + L_OFF_AH + row*128;
        rxa[mt] = row & 7;
    }
    uint32_t RB[2]; int rxb[2];
    const int u_b = (lane >> 3) & 1;
    #pragma unroll
    for (int p = 0; p < 2; p++) {
        int ch = warp_n*32 + p*16 + ((lane & 16) >> 1) + (lane & 7);
        RB[p] = sb + L_OFF_BH + ch*128;
        rxb[p] = ch & 7;
    }

    float acc[4][4][4];
    #pragma unroll
    for (int mt = 0; mt < 4; mt++)
        #pragma unroll
        for (int nt = 0; nt < 4; nt++)
            #pragma unroll
            for (int r4 = 0; r4 < 4; r4++) acc[mt][nt][r4] = 0.f;

    #pragma unroll
    for (int ks = 0; ks < 4; ks++) {
        uint32_t ah[4][4], al[4][4], bh[2][4], bl[2][4];
        #pragma unroll
        for (int mt = 0; mt < 4; mt++) {
            uint32_t off = (uint32_t)(((ks*2 + u_a) ^ rxa[mt]) << 4);
            ldsm4(ah[mt], RA[mt] + off);
            ldsm4(al[mt], RA[mt] + 16384 + off);
        }
        #pragma unroll
        for (int p = 0; p < 2; p++) {
            uint32_t off = (uint32_t)(((ks*2 + u_b) ^ rxb[p]) << 4);
            ldsm4(bh[p], RB[p] + off);
            ldsm4(bl[p], RB[p] + 16384 + off);
        }
        #pragma unroll
        for (int mt = 0; mt < 4; mt++)
            #pragma unroll
            for (int nt = 0; nt < 4; nt++) {
                int p = nt >> 1, ix = (nt & 1) * 2;
                mma16816(acc[mt][nt], ah[mt], bh[p][ix], bh[p][ix+1]);
                mma16816(acc[mt][nt], al[mt], bh[p][ix], bh[p][ix+1]);
                mma16816(acc[mt][nt], ah[mt], bl[p][ix], bl[p][ix+1]);
            }
    }
    __syncthreads();

    float* vsm = (float*)smem;
    #pragma unroll
    for (int mt = 0; mt < 4; mt++)
        #pragma unroll
        for (int nt = 0; nt < 4; nt++)
            #pragma unroll
            for (int r4 = 0; r4 < 4; r4++) {
                int row = warp_m*64 + mt*16 + grp + ((r4 & 2) ? 8 : 0);
                int col = warp_n*32 + nt*8 + 2*tig + (r4 & 1);
                vsm[col*133 + row] = acc[mt][nt][r4];
            }
    __syncthreads();

    {
        int c = tid & 127, halfp = tid >> 7;
        int idx = c0 + c;
        bool isP = (idx < COUT);
        int ch = isP ? idx : idx - COUT;
        float* gout = isP ? g_p : g_d;
        float sn = 0.f, sn2 = 0.f;
        const float* vc = vsm + c*133 + halfp*64;
        int bn0 = blockIdx.x*32 + halfp*16;
        #pragma unroll
        for (int i = 0; i < 16; i++) {
            float v0 = vc[i*4 + 0], v1 = vc[i*4 + 1], v2 = vc[i*4 + 2];
            size_t row = (size_t)(bn0 + i) * 3;
            gout[(row + 0)*COUT + ch] = v0;
            gout[(row + 1)*COUT + ch] = v1;
            gout[(row + 2)*COUT + ch] = v2;
            if (isP) {
                float q  = v0*v0 + v1*v1 + v2*v2;
                sn += sqrtf(q) + VEPS; sn2 += q;
            }
        }
        if (isP) {
            atomicAdd(&ssum[ch & 127], sn);
            atomicAdd(&ssum[128 + (ch & 127)], sn2);
        }
    }
    __syncthreads();
    if (c0 == 0 && tid < COUT) {
        atomicAdd(&sums[tid],        (double)ssum[tid & 127]);
        atomicAdd(&sums[COUT + tid], (double)ssum[128 + (tid & 127)]);
    }
}

// --------------------------- apply BN + VN-leaky (inline finalize) ----------
// DST: 0 = g_hA (hi/lo), 1 = g_hB (hi/lo), 2 = g_h16 (fp16 single)
template<int COUT, int DST, int WHICH>
__global__ __launch_bounds__(256) void apply_bn_leaky(const float* __restrict__ ga,
                                                      const float* __restrict__ be) {
    const double* s = (WHICH == 2) ? g_s2 : (WHICH == 3) ? g_s3 : g_s4;
    int i = blockIdx.x * 256 + threadIdx.x;
    if (i >= BN * COUT) return;
    int bn = i / COUT, c = i % COUT;
    const double cnt = (double)BN;
    double mud = s[c] / cnt;
    float  mu  = (float)mud;
    float  rs  = rsqrtf((float)(s[COUT + c] / cnt - mud*mud) + BNEPS);
    size_t r = (size_t)bn * 3;
    float p0 = g_p[(r+0)*COUT + c], p1 = g_p[(r+1)*COUT + c], p2 = g_p[(r+2)*COUT + c];
    float q  = p0*p0 + p1*p1 + p2*p2;
    float inv = rsqrtf(fmaxf(q, 1e-30f));
    float nr = q*inv + VEPS;
    float sc = (ga[c]*(nr - mu)*rs + be[c]) * inv;
    p0 *= sc; p1 *= sc; p2 *= sc;
    float d0 = g_d[(r+0)*COUT + c], d1 = g_d[(r+1)*COUT + c], d2 = g_d[(r+2)*COUT + c];
    float dot = p0*d0 + p1*d1 + p2*d2;
    if (dot < 0.f) {
        float s2 = __fdividef(dot, d0*d0 + d1*d1 + d2*d2 + VEPS);
        p0 -= s2*d0; p1 -= s2*d1; p2 -= s2*d2;
    }
    size_t ro = (size_t)bn * 4;
    if (DST == 2) {
        g_h16[(ro+0)*COUT + c] = __float2half_rn(p0);
        g_h16[(ro+1)*COUT + c] = __float2half_rn(p1);
        g_h16[(ro+2)*COUT + c] = __float2half_rn(p2);
        g_h16[(ro+3)*COUT + c] = __float2half_rn(0.f);
    } else {
        __half* hh = (DST == 0) ? g_hAh : g_hBh;
        __half* hl = (DST == 0) ? g_hAl : g_hBl;
        float v[3] = {p0, p1, p2};
        #pragma unroll
        for (int comp = 0; comp < 3; comp++) {
            __half hv = __float2half_rn(v[comp]);
            hh[(ro+comp)*COUT + c] = hv;
            hl[(ro+comp)*COUT + c] = __float2half_rn(v[comp] - __half2float(hv));
        }
        hh[(ro+3)*COUT + c] = __float2half_rn(0.f);
        hl[(ro+3)*COUT + c] = __float2half_rn(0.f);
    }
}

// --------------------------- conv5: fp16 mma.sync (R13 shape) ----------------
#define C5_OFF_A   0
#define C5_OFF_BH  32768
#define C5_OFF_BL  65536
#define C5_OFF_ACC 98304
#define C5_SMEM    102400

__device__ __forceinline__ int c5_swz(int row, int b8) {   // b8: byte off in 256B row
    return (row << 8) + (b8 ^ (((row & 3) << 5) | ((row & 4) << 2)));
}

__global__ __launch_bounds__(256, 2) void conv5_hmma() {
    extern __shared__ char smem[];
    const uint32_t sb = smem_u32(smem);
    float* accf = (float*)(smem + C5_OFF_ACC);

    const int tid  = threadIdx.x;
    const int lane = tid & 31, warp = tid >> 5;
    const int grp  = lane >> 2, tig = lane & 3;
    const int warp_m = warp >> 2, warp_n = warp & 3;
    const int m0 = blockIdx.x * 128;
    const int c0 = blockIdx.y * 128;

    for (int i = tid; i < 1024; i += 256) accf[i] = 0.f;

    #pragma unroll
    for (int i = 0; i < 16; i++) {
        int e = tid + i*256, r = e >> 5, q = e & 31;
        uint2 hv = *(const uint2*)(g_h16 + (size_t)(m0 + r)*128 + q*4);
        *(uint2*)(smem + C5_OFF_A + c5_swz(r, q*8)) = hv;
    }
    #pragma unroll
    for (int i = 0; i < 16; i++) {
        int e = tid + i*256, r = e >> 5, q = e & 31;
        size_t off = (size_t)(c0 + r)*128 + q*4;
        int sw = c5_swz(r, q*8);
        *(uint2*)(smem + C5_OFF_BH + sw) = *(const uint2*)(g_w5h + off);
        *(uint2*)(smem + C5_OFF_BL + sw) = *(const uint2*)(g_w5l + off);
    }
    __syncthreads();

    uint32_t PA[4], XA[4];
    #pragma unroll
    for (int mt = 0; mt < 4; mt++) {
        int row = warp_m*64 + mt*16 + (lane & 15);
        XA[mt] = (row & 3) << 5;
        PA[mt] = sb + C5_OFF_A + row*256 + ((lane & 16) ^ ((row & 4) << 2));
    }
    uint32_t PBh[2], PBl[2], XB[2];
    #pragma unroll
    for (int p = 0; p < 2; p++) {
        int ch = warp_n*32 + p*16 + ((lane & 16) >> 1) + (lane & 7);
        XB[p]  = (ch & 3) << 5;
        uint32_t off = ch*256 + (((lane & 8) << 1) ^ ((ch & 4) << 2));
        PBh[p] = sb + C5_OFF_BH + off;
        PBl[p] = sb + C5_OFF_BL + off;
    }

    float acc[4][4][4];
    #pragma unroll
    for (int mt = 0; mt < 4; mt++)
        #pragma unroll
        for (int nt = 0; nt < 4; nt++)
            #pragma unroll
            for (int r4 = 0; r4 < 4; r4++) acc[mt][nt][r4] = 0.f;

    #pragma unroll
    for (int ks = 0; ks < 8; ks++) {
        uint32_t a[4][4], bh[2][4], bl[2][4];
        #pragma unroll
        for (int mt = 0; mt < 4; mt++) ldsm4(a[mt], PA[mt] + ((ks*32) ^ XA[mt]));
        #pragma unroll
        for (int p = 0; p < 2; p++) {
            ldsm4(bh[p], PBh[p] + ((ks*32) ^ XB[p]));
            ldsm4(bl[p], PBl[p] + ((ks*32) ^ XB[p]));
        }
        #pragma unroll
        for (int mt = 0; mt < 4; mt++)
            #pragma unroll
            for (int nt = 0; nt < 4; nt++) {
                int p = nt >> 1, ix = (nt & 1) * 2;
                mma16816(acc[mt][nt], a[mt], bh[p][ix], bh[p][ix+1]);
                mma16816(acc[mt][nt], a[mt], bl[p][ix], bl[p][ix+1]);
            }
    }
    __syncthreads();

    float* vsm = (float*)smem;
    #pragma unroll
    for (int mt = 0; mt < 4; mt++)
        #pragma unroll
        for (int nt = 0; nt < 4; nt++)
            #pragma unroll
            for (int r4 = 0; r4 < 4; r4++) {
                int row = warp_m*64 + mt*16 + grp + ((r4 & 2) ? 8 : 0);
                int col = warp_n*32 + nt*8 + 2*tig + (r4 & 1);
                vsm[col*133 + row] = acc[mt][nt][r4];
            }
    __syncthreads();

    {
        int c = tid & 127, halfp = tid >> 7;
        float sn = 0.f, sn2 = 0.f;
        float sv0 = 0.f, sv1 = 0.f, sv2 = 0.f;
        float sw0 = 0.f, sw1 = 0.f, sw2 = 0.f;
        const float* vc = vsm + c*133 + halfp*64;
        #pragma unroll
        for (int i = 0; i < 8; i++) {
            float v0 = vc[i*4 + 0], v1 = vc[i*4 + 1], v2 = vc[i*4 + 2];
            float q  = v0*v0 + v1*v1 + v2*v2;
            float inv = rsqrtf(fmaxf(q, 1e-30f));
            float nr = q*inv + VEPS;
            sn += nr; sn2 += q;
            sv0 += v0; sv1 += v1; sv2 += v2;
            sw0 += v0*inv; sw1 += v1*inv; sw2 += v2*inv;
        }
        #pragma unroll
        for (int i = 8; i < 16; i++) {
            float v0 = vc[i*4 + 0], v1 = vc[i*4 + 1], v2 = vc[i*4 + 2];
            float q  = v0*v0 + v1*v1 + v2*v2;
            float inv = rsqrtf(fmaxf(q, 1e-30f));
            float nr = q*inv + VEPS;
            sn += nr; sn2 += q;
            sv0 += v0; sv1 += v1; sv2 += v2;
            sw0 += v0*inv; sw1 += v1*inv; sw2 += v2*inv;
        }
        atomicAdd(&accf[c*8 + 0], sn);
        atomicAdd(&accf[c*8 + 1], sn2);
        atomicAdd(&accf[c*8 + 2], sv0);
        atomicAdd(&accf[c*8 + 3], sv1);
        atomicAdd(&accf[c*8 + 4], sv2);
        atomicAdd(&accf[c*8 + 5], sw0);
        atomicAdd(&accf[c*8 + 6], sw1);
        atomicAdd(&accf[c*8 + 7], sw2);
    }
    __syncthreads();

    const int b = blockIdx.x / 128;
    for (int i = tid; i < 1024; i += 256) {
        int c = i >> 3, q = i & 7;
        float vv = accf[i];
        int cg = c0 + c;
        if (q == 0)      atomicAdd(&g_s5[cg],        (double)vv);
        else if (q == 1) atomicAdd(&g_s5[1024 + cg], (double)vv);
        else if (q < 5)  atomicAdd(&g_sumv [(b*1024 + cg)*3 + (q-2)], vv);
        else             atomicAdd(&g_sumvn[(b*1024 + cg)*3 + (q-5)], vv);
    }
}

// --------------------------- final output ------------------------------------
__global__ void final_out(const float* __restrict__ g5, const float* __restrict__ b5,
                          float* __restrict__ out) {
    int c = blockIdx.x * 256 + threadIdx.x;
    if (c >= 1024) return;
    double mu  = g_s5[c]        / (double)BN;
    double var = g_s5[1024 + c] / (double)BN - mu*mu;
    float rs  = (float)(1.0 / sqrt(var + (double)BNEPS));
    float a   = g5[c] * rs;
    float t   = a * (float)mu - b5[c];
    #pragma unroll
    for (int b = 0; b < Bc; b++)
        #pragma unroll
        for (int comp = 0; comp < 3; comp++) {
            int gi = (b*1024 + c)*3 + comp;
            out[gi] = a * (g_sumv[gi] * (1.f/(float)Nc))
                    - t * (g_sumvn[gi] * (1.f/(float)Nc));
        }
}

// ---------------------------------------------------------------------------
extern "C" void kernel_launch(void* const* d_in, const int* in_sizes, int n_in,
                              void* d_out, int out_size) {
    const float* x  = (const float*)d_in[0];
    const float* W1 = (const float*)d_in[1];
    const float* D1 = (const float*)d_in[2];
    const float* g1 = (const float*)d_in[3];
    const float* b1 = (const float*)d_in[4];
    const float* W2 = (const float*)d_in[5];
    const float* D2 = (const float*)d_in[6];
    const float* g2 = (const float*)d_in[7];
    const float* b2 = (const float*)d_in[8];
    const float* W3 = (const float*)d_in[9];
    const float* D3 = (const float*)d_in[10];
    const float* g3 = (const float*)d_in[11];
    const float* b3 = (const float*)d_in[12];
    const float* W4 = (const float*)d_in[13];
    const float* D4 = (const float*)d_in[14];
    const float* g4 = (const float*)d_in[15];
    const float* b4 = (const float*)d_in[16];
    const float* W5 = (const float*)d_in[17];
    const float* g5 = (const float*)d_in[18];
    const float* b5 = (const float*)d_in[19];
    float* out = (float*)d_out;

    cudaFuncSetAttribute(knn_kernel, cudaFuncAttributeMaxDynamicSharedMemorySize, KNN_SMEM);
    cudaFuncSetAttribute(conv5_hmma, cudaFuncAttributeMaxDynamicSharedMemorySize, C5_SMEM);
    cudaFuncSetAttribute(gemm_hmma<64, 0, 2>, cudaFuncAttributeMaxDynamicSharedMemorySize, L_SMEM);
    cudaFuncSetAttribute(gemm_hmma<64, 1, 3>, cudaFuncAttributeMaxDynamicSharedMemorySize, L_SMEM);
    cudaFuncSetAttribute(gemm_hmma<128, 0, 4>, cudaFuncAttributeMaxDynamicSharedMemorySize, L_SMEM);

    prep_kernel<<<512, 256>>>(W2, D2, W3, D3, W4, D4, W5);  // my idx 0
    knn_kernel<<<dim3(Nc/32, Bc), 1024, KNN_SMEM>>>(x);     // my idx 1

    block1_stats<<<dim3(Nc/2, Bc), 128>>>(x, W1);           // my idx 2
    block1_apply<<<dim3(Nc/2, Bc), 128>>>(x, W1, D1, g1, b1);  // my idx 3 == profiled

    gemm_hmma<64, 0, 2><<<dim3(512, 1), 256, L_SMEM>>>();
    apply_bn_leaky<64, 1, 2><<<(BN*64 + 255)/256, 256>>>(g2, b2);

    gemm_hmma<64, 1, 3><<<dim3(512, 1), 256, L_SMEM>>>();
    apply_bn_leaky<64, 0, 3><<<(BN*64 + 255)/256, 256>>>(g3, b3);

    gemm_hmma<128, 0, 4><<<dim3(512, 2), 256, L_SMEM>>>();
    apply_bn_leaky<128, 2, 4><<<(BN*128 + 255)/256, 256>>>(g4, b4);

    conv5_hmma<<<dim3(65536/128, 1024/128), 256, C5_SMEM>>>();
    final_out<<<4, 256>>>(g5, b5, out);
}

// round 16
// speedup vs baseline: 1.1099x; 1.0186x over previous
#include <cuda_runtime.h>
#include <cuda_fp16.h>
#include <math.h>
#include <stdint.h>

#define Bc   4
#define Nc   4096
#define Kc   20
#define BN   (Bc*Nc)          // 16384
#define VEPS 1e-6f
#define BNEPS 1e-5f

// ---------------- persistent device scratch (no allocations allowed) -------
__device__ int    g_idx[Bc*Nc*Kc];
__device__ __half g_hAh[BN*4*64], g_hAl[BN*4*64];   // block1 output (hi/lo)
__device__ __half g_h16[BN*4*128];                  // fp16 h4 for conv5
__device__ float  g_p [BN*3*128];                   // p/d set A (layers 2,4)
__device__ float  g_d [BN*3*128];
__device__ float  g_pB[BN*3*64];                    // p/d set B (layer 3)
__device__ float  g_dB[BN*3*64];
__device__ double g_s1[128];
__device__ double g_s2[128];
__device__ double g_s3[128];
__device__ double g_s4[256];
__device__ double g_s5[2048];
__device__ float  g_sumv [Bc*1024*3];
__device__ float  g_sumvn[Bc*1024*3];
// pre-split weights
__device__ __half g_wd2h[128*64], g_wd2l[128*64];   // [W2;D2]
__device__ __half g_wd3h[128*64], g_wd3l[128*64];   // [W3;D3]
__device__ __half g_wd4h[256*64], g_wd4l[256*64];   // [W4;D4]
__device__ __half g_w5h[1024*128], g_w5l[1024*128];

// --------------------------- prep: zero stats + split weights ---------------
__global__ void prep_kernel(const float* __restrict__ W2, const float* __restrict__ D2,
                            const float* __restrict__ W3, const float* __restrict__ D3,
                            const float* __restrict__ W4, const float* __restrict__ D4,
                            const float* __restrict__ W5) {
    int i = blockIdx.x * 256 + threadIdx.x;          // grid 512*256 = 131072
    if (i < 128) { g_s1[i] = 0.0; g_s2[i] = 0.0; g_s3[i] = 0.0; }
    if (i < 256) { g_s4[i] = 0.0; }
    if (i < 2048){ g_s5[i] = 0.0; }
    if (i < Bc*1024*3) { g_sumv[i] = 0.f; g_sumvn[i] = 0.f; }
    {
        float v = W5[i];
        __half h = __float2half_rn(v);
        g_w5h[i] = h;
        g_w5l[i] = __float2half_rn(v - __half2float(h));
    }
    if (i < 16384) {
        int row = i >> 6, col = i & 63;
        float v = (row < 128) ? W4[row*64 + col] : D4[(row-128)*64 + col];
        __half h = __float2half_rn(v);
        g_wd4h[i] = h;
        g_wd4l[i] = __float2half_rn(v - __half2float(h));
    }
    if (i < 8192) {
        int row = i >> 6, col = i & 63;
        float v2 = (row < 64) ? W2[row*64 + col] : D2[(row-64)*64 + col];
        __half h2 = __float2half_rn(v2);
        g_wd2h[i] = h2;
        g_wd2l[i] = __float2half_rn(v2 - __half2float(h2));
        float v3 = (row < 64) ? W3[row*64 + col] : D3[(row-64)*64 + col];
        __half h3 = __float2half_rn(v3);
        g_wd3h[i] = h3;
        g_wd3l[i] = __float2half_rn(v3 - __half2float(h3));
    }
}

// ===================== mma/ldmatrix helpers ==================================
__device__ __forceinline__ uint32_t smem_u32(const void* p) {
    uint32_t a;
    asm("{ .reg .u64 t; cvta.to.shared.u64 t, %1; cvt.u32.u64 %0, t; }" : "=r"(a) : "l"(p));
    return a;
}
__device__ __forceinline__ void ldsm4(uint32_t* r, uint32_t addr) {
    asm volatile("ldmatrix.sync.aligned.m8n8.x4.shared.b16 {%0,%1,%2,%3}, [%4];"
        : "=r"(r[0]), "=r"(r[1]), "=r"(r[2]), "=r"(r[3]) : "r"(addr));
}
__device__ __forceinline__ void mma16816(float* c, const uint32_t* a, uint32_t b0, uint32_t b1) {
    asm volatile("mma.sync.aligned.m16n8k16.row.col.f32.f16.f16.f32 "
        "{%0,%1,%2,%3}, {%4,%5,%6,%7}, {%8,%9}, {%0,%1,%2,%3};"
        : "+f"(c[0]), "+f"(c[1]), "+f"(c[2]), "+f"(c[3])
        : "r"(a[0]), "r"(a[1]), "r"(a[2]), "r"(a[3]), "r"(b0), "r"(b1));
}
__device__ __forceinline__ uint32_t packh2f(float lo, float hi) {
    uint32_t r; asm("cvt.rn.f16x2.f32 %0, %1, %2;" : "=r"(r) : "f"(hi), "f"(lo)); return r;
}

// --------------------------- KNN: float4 score scan + redux argmax ----------
#define KNN_SMEM (Nc*16)                 // 65536 bytes

__device__ __forceinline__ uint32_t fkey(float f) {
    uint32_t b = __float_as_uint(f);
    return b ^ (uint32_t)(((int32_t)b >> 31) | 0x80000000);
}

__global__ __launch_bounds__(1024) void knn_kernel(const float* __restrict__ x) {
    extern __shared__ float4 pts[];

    const int tid = threadIdx.x;
    const int b = blockIdx.y;
    const float4* xb4 = (const float4*)(x + (size_t)b * Nc * 3);

    {
        float4 v0 = xb4[tid*3 + 0];
        float4 v1 = xb4[tid*3 + 1];
        float4 v2 = xb4[tid*3 + 2];
        int p = tid * 4;
        pts[p+0] = make_float4(v0.x, v0.y, v0.z, -(v0.x*v0.x + v0.y*v0.y + v0.z*v0.z));
        pts[p+1] = make_float4(v0.w, v1.x, v1.y, -(v0.w*v0.w + v1.x*v1.x + v1.y*v1.y));
        pts[p+2] = make_float4(v1.z, v1.w, v2.x, -(v1.z*v1.z + v1.w*v1.w + v2.x*v2.x));
        pts[p+3] = make_float4(v2.y, v2.z, v2.w, -(v2.y*v2.y + v2.z*v2.z + v2.w*v2.w));
    }
    __syncthreads();

    const int w = tid >> 5, lane = tid & 31;
    const int n = blockIdx.x * 32 + w;

    const float4 q = pts[n];
    const float qx2 = 2.f*q.x, qy2 = 2.f*q.y, qz2 = 2.f*q.z;

    uint32_t mk[4]; uint32_t mi4[4];
    uint32_t msk[4] = {0u, 0u, 0u, 0u};

    #pragma unroll
    for (int c = 0; c < 4; c++) {
        float cm = -3.4e38f; int cj = 0;
        #pragma unroll 8
        for (int i = 0; i < 32; i++) {
            int j = lane + ((c*32 + i) << 5);
            float4 a = pts[j];
            float d = fmaf(a.x, qx2, fmaf(a.y, qy2, fmaf(a.z, qz2, a.w)));
            if (d > cm) { cm = d; cj = j; }
        }
        mk[c] = fkey(cm); mi4[c] = (uint32_t)cj;
    }
    uint32_t bk = mk[0], bj = mi4[0];
    #pragma unroll
    for (int c = 1; c < 4; c++)
        if (mk[c] > bk || (mk[c] == bk && mi4[c] < bj)) { bk = mk[c]; bj = mi4[c]; }

    for (int k = 0; k < Kc; k++) {
        uint32_t best = __reduce_max_sync(0xffffffffu, bk);
        uint32_t cand = (bk == best) ? bj : 0xffffffffu;
        uint32_t j = __reduce_min_sync(0xffffffffu, cand);
        if (lane == 0) g_idx[((size_t)b*Nc + n)*Kc + k] = (int)j;
        if (k == Kc - 1) break;

        const int wl = (int)(j & 31);
        const int C  = (int)(j >> 10);
        const int ib = (int)((j >> 5) & 31);
        if (lane == wl) {
            if (C == 0) msk[0] |= 1u << ib;
            else if (C == 1) msk[1] |= 1u << ib;
            else if (C == 2) msk[2] |= 1u << ib;
            else msk[3] |= 1u << ib;
        }
        uint32_t myb = (C == 0) ? msk[0] : (C == 1) ? msk[1]
                     : (C == 2) ? msk[2] : msk[3];
        uint32_t bm = __shfl_sync(0xffffffffu, myb, wl);

        int jj = wl + ((C*32 + lane) << 5);
        float4 a = pts[jj];
        float d = fmaf(a.x, qx2, fmaf(a.y, qy2, fmaf(a.z, qz2, a.w)));
        uint32_t ck = ((bm >> lane) & 1u) ? 0u : fkey(d);
        uint32_t best2 = __reduce_max_sync(0xffffffffu, ck);
        uint32_t cand2 = (ck == best2 && ck != 0u) ? (uint32_t)jj : 0xffffffffu;
        uint32_t j2 = __reduce_min_sync(0xffffffffu, cand2);

        if (lane == wl) {
            if (C == 0)      { mk[0] = best2; mi4[0] = j2; }
            else if (C == 1) { mk[1] = best2; mi4[1] = j2; }
            else if (C == 2) { mk[2] = best2; mi4[2] = j2; }
            else             { mk[3] = best2; mi4[3] = j2; }
            bk = mk[0]; bj = mi4[0];
            #pragma unroll
            for (int c = 1; c < 4; c++)
                if (mk[c] > bk || (mk[c] == bk && mi4[c] < bj)) { bk = mk[c]; bj = mi4[c]; }
        }
    }
}

// --------------------------- block1 (3ch edge feat -> 64) -------------------
__device__ __forceinline__ void build_f(const float* __restrict__ x, int b, int n0,
                                        float f[2][Kc][9]) {
    int t = threadIdx.x;
    if (t < 2*Kc) {
        int ln = t / Kc, k = t % Kc;
        int n = n0 + ln;
        const float* xb = x + (size_t)b * Nc * 3;
        float cx = xb[n*3+0], cy = xb[n*3+1], cz = xb[n*3+2];
        int j = g_idx[((size_t)b*Nc + n)*Kc + k];
        float ax = xb[j*3+0], ay = xb[j*3+1], az = xb[j*3+2];
        f[ln][k][0] = ax - cx; f[ln][k][1] = ay - cy; f[ln][k][2] = az - cz;
        f[ln][k][3] = cx;      f[ln][k][4] = cy;      f[ln][k][5] = cz;
        f[ln][k][6] = ay*cz - az*cy;
        f[ln][k][7] = az*cx - ax*cz;
        f[ln][k][8] = ax*cy - ay*cx;
    }
}

__global__ __launch_bounds__(128, 12) void block1_stats(const float* __restrict__ x,
                                                        const float* __restrict__ W1) {
    int b = blockIdx.y, n0 = blockIdx.x * 2;
    __shared__ float f[2][Kc][9];
    __shared__ float red[2][128];
    build_f(x, b, n0, f);
    __syncthreads();
    int t = threadIdx.x;
    int ln = t >> 6, c = t & 63;
    float w0 = W1[c*3+0], w1 = W1[c*3+1], w2 = W1[c*3+2];
    float sn = 0.f, sn2 = 0.f;
    #pragma unroll 5
    for (int k = 0; k < Kc; k++) {
        const float* fk = f[ln][k];
        float p0 = w0*fk[0] + w1*fk[3] + w2*fk[6];
        float p1 = w0*fk[1] + w1*fk[4] + w2*fk[7];
        float p2 = w0*fk[2] + w1*fk[5] + w2*fk[8];
        float nr = sqrtf(p0*p0 + p1*p1 + p2*p2) + VEPS;
        sn += nr; sn2 += nr*nr;
    }
    red[ln][c] = sn; red[ln][64 + c] = sn2;
    __syncthreads();
    if (t < 64) {
        atomicAdd(&g_s1[t],      (double)red[0][t]      + (double)red[1][t]);
        atomicAdd(&g_s1[64 + t], (double)red[0][64 + t] + (double)red[1][64 + t]);
    }
}

__global__ __launch_bounds__(128, 12) void block1_apply(const float* __restrict__ x,
                                                        const float* __restrict__ W1,
                                                        const float* __restrict__ D1,
                                                        const float* __restrict__ g1,
                                                        const float* __restrict__ b1) {
    int b = blockIdx.y, n0 = blockIdx.x * 2;
    __shared__ float f[2][Kc][9];
    build_f(x, b, n0, f);
    __syncthreads();
    int t = threadIdx.x;
    int ln = t >> 6, c = t & 63;
    float w0 = W1[c*3+0], w1 = W1[c*3+1], w2 = W1[c*3+2];
    float e0 = D1[c*3+0], e1 = D1[c*3+1], e2 = D1[c*3+2];
    const double cnt = (double)(Bc*Nc*Kc);
    double mud = g_s1[c] / cnt;
    float  mu  = (float)mud;
    float  rs  = rsqrtf((float)(g_s1[64 + c] / cnt - mud*mud) + BNEPS);
    float ga = g1[c], be = b1[c];
    float a0 = 0.f, a1 = 0.f, a2 = 0.f;
    #pragma unroll 5
    for (int k = 0; k < Kc; k++) {
        const float* fk = f[ln][k];
        float p0 = w0*fk[0] + w1*fk[3] + w2*fk[6];
        float p1 = w0*fk[1] + w1*fk[4] + w2*fk[7];
        float p2 = w0*fk[2] + w1*fk[5] + w2*fk[8];
        float q  = p0*p0 + p1*p1 + p2*p2;
        float inv = rsqrtf(fmaxf(q, 1e-30f));
        float nr = q*inv + VEPS;
        float sc = (ga*(nr - mu)*rs + be) * inv;
        p0 *= sc; p1 *= sc; p2 *= sc;
        float d0 = e0*fk[0] + e1*fk[3] + e2*fk[6];
        float d1 = e0*fk[1] + e1*fk[4] + e2*fk[7];
        float d2 = e0*fk[2] + e1*fk[5] + e2*fk[8];
        float dot = p0*d0 + p1*d1 + p2*d2;
        if (dot < 0.f) {
            float s2 = __fdividef(dot, d0*d0 + d1*d1 + d2*d2 + VEPS);
            p0 -= s2*d0; p1 -= s2*d1; p2 -= s2*d2;
        }
        a0 += p0; a1 += p1; a2 += p2;
    }
    size_t bn = (size_t)b*Nc + n0 + ln;
    const float inv = 1.f / (float)Kc;
    float v[3] = {a0*inv, a1*inv, a2*inv};
    #pragma unroll
    for (int comp = 0; comp < 3; comp++) {
        __half hv = __float2half_rn(v[comp]);
        g_hAh[(bn*4 + comp)*64 + c] = hv;
        g_hAl[(bn*4 + comp)*64 + c] = __float2half_rn(v[comp] - __half2float(hv));
    }
    g_hAh[(bn*4 + 3)*64 + c] = __float2half_rn(0.f);
    g_hAl[(bn*4 + 3)*64 + c] = __float2half_rn(0.f);
}

// --------------------------- layers 2-4: HMMA GEMM + fused apply staging ----
// APPLY=0: A from g_hAh/g_hAl (gemm2). APPLY=1: A = BN+leaky applied inline
// from previous layer's p/d (64ch) using that layer's stats/gamma/beta.
// p/d ping-pong: gemm2 -> set A; gemm3 reads A writes B; gemm4 reads B writes A.
#define L_OFF_AH 0
#define L_OFF_AL 16384
#define L_OFF_BH 32768
#define L_OFF_BL 49152
#define L_OFF_SS 68096                   // ssum: 256 floats
#define L_OFF_PM 69120                   // mu/rstd/ga/be: 4*64 floats
#define L_SMEM   70144

template<int COUT, int WHICH, int APPLY>
__global__ __launch_bounds__(256, 2) void gemm_hmma(const float* __restrict__ gaPrev,
                                                    const float* __restrict__ bePrev) {
    extern __shared__ char smem[];
    const uint32_t sb = smem_u32(smem);
    const int tid  = threadIdx.x;
    const int lane = tid & 31, warp = tid >> 5;
    const int grp  = lane >> 2, tig = lane & 3;
    const int warp_m = warp >> 2, warp_n = warp & 3;
    const int m0 = blockIdx.x * 128;
    const int c0 = blockIdx.y * 128;
    const __half* __restrict__ wh = (WHICH == 2) ? g_wd2h : (WHICH == 3) ? g_wd3h : g_wd4h;
    const __half* __restrict__ wl = (WHICH == 2) ? g_wd2l : (WHICH == 3) ? g_wd3l : g_wd4l;
    double* sums = (WHICH == 2) ? g_s2 : (WHICH == 3) ? g_s3 : g_s4;
    const float* __restrict__ pSrc = (WHICH == 3) ? g_p  : g_pB;
    const float* __restrict__ dSrc = (WHICH == 3) ? g_d  : g_dB;
    const double* sPrev = (WHICH == 3) ? g_s2 : g_s3;
    float* pDst = (WHICH == 3) ? g_pB : g_p;
    float* dDst = (WHICH == 3) ? g_dB : g_d;

    float* ssum = (float*)(smem + L_OFF_SS);
    ssum[tid] = 0.f;

    if (APPLY) {
        float* prm = (float*)(smem + L_OFF_PM);   // mu[64], rstd[64], ga[64], be[64]
        if (tid < 64) {
            double mud = sPrev[tid] / (double)BN;
            prm[tid]       = (float)mud;
            prm[64 + tid]  = rsqrtf((float)(sPrev[64 + tid] / (double)BN - mud*mud) + BNEPS);
            prm[128 + tid] = gaPrev[tid];
            prm[192 + tid] = bePrev[tid];
        }
        __syncthreads();
        // thread: pt = tid>>3 (0..31), cg = tid&7 (8 channels)
        const int pt = tid >> 3, cg = tid & 7;
        const size_t ptg = (size_t)(blockIdx.x*32 + pt);
        float p[3][8], d[3][8];
        #pragma unroll
        for (int comp = 0; comp < 3; comp++) {
            size_t off = (ptg*3 + comp)*64 + cg*8;
            *(float4*)&p[comp][0] = *(const float4*)(pSrc + off);
            *(float4*)&p[comp][4] = *(const float4*)(pSrc + off + 4);
            *(float4*)&d[comp][0] = *(const float4*)(dSrc + off);
            *(float4*)&d[comp][4] = *(const float4*)(dSrc + off + 4);
        }
        #pragma unroll
        for (int j = 0; j < 8; j++) {
            int c = cg*8 + j;
            float q  = p[0][j]*p[0][j] + p[1][j]*p[1][j] + p[2][j]*p[2][j];
            float iv = rsqrtf(fmaxf(q, 1e-30f));
            float nr = q*iv + VEPS;
            float sc = (prm[128+c]*(nr - prm[c])*prm[64+c] + prm[192+c]) * iv;
            float p0 = p[0][j]*sc, p1 = p[1][j]*sc, p2 = p[2][j]*sc;
            float dot = p0*d[0][j] + p1*d[1][j] + p2*d[2][j];
            if (dot < 0.f) {
                float s2 = __fdividef(dot, d[0][j]*d[0][j] + d[1][j]*d[1][j] + d[2][j]*d[2][j] + VEPS);
                p0 -= s2*d[0][j]; p1 -= s2*d[1][j]; p2 -= s2*d[2][j];
            }
            p[0][j] = p0; p[1][j] = p1; p[2][j] = p2;
        }
        #pragma unroll
        for (int comp = 0; comp < 4; comp++) {
            int row = pt*4 + comp;
            uint32_t sw = row*128 + ((cg ^ (row & 7)) << 4);
            uint4 hh, ll;
            if (comp < 3) {
                float h0 = __half2float(__float2half_rn(p[comp][0]));
                float h1 = __half2float(__float2half_rn(p[comp][1]));
                float h2 = __half2float(__float2half_rn(p[comp][2]));
                float h3 = __half2float(__float2half_rn(p[comp][3]));
                float h4 = __half2float(__float2half_rn(p[comp][4]));
                float h5 = __half2float(__float2half_rn(p[comp][5]));
                float h6 = __half2float(__float2half_rn(p[comp][6]));
                float h7 = __half2float(__float2half_rn(p[comp][7]));
                hh = make_uint4(packh2f(h0,h1), packh2f(h2,h3), packh2f(h4,h5), packh2f(h6,h7));
                ll = make_uint4(packh2f(p[comp][0]-h0, p[comp][1]-h1),
                                packh2f(p[comp][2]-h2, p[comp][3]-h3),
                                packh2f(p[comp][4]-h4, p[comp][5]-h5),
                                packh2f(p[comp][6]-h6, p[comp][7]-h7));
            } else {
                hh = make_uint4(0u, 0u, 0u, 0u);
                ll = make_uint4(0u, 0u, 0u, 0u);
            }
            *(uint4*)(smem + L_OFF_AH + sw) = hh;
            *(uint4*)(smem + L_OFF_AL + sw) = ll;
        }
    } else {
        #pragma unroll
        for (int i = 0; i < 4; i++) {
            int e = tid + i*256, r = e >> 3, un = e & 7;
            size_t off = (size_t)(m0 + r)*64 + un*8;
            uint32_t sw = r*128 + ((un ^ (r & 7)) << 4);
            *(uint4*)(smem + L_OFF_AH + sw) = *(const uint4*)(g_hAh + off);
            *(uint4*)(smem + L_OFF_AL + sw) = *(const uint4*)(g_hAl + off);
        }
    }
    #pragma unroll
    for (int i = 0; i < 4; i++) {
        int e = tid + i*256, r = e >> 3, un = e & 7;
        size_t off = (size_t)(c0 + r)*64 + un*8;
        uint32_t sw = r*128 + ((un ^ (r & 7)) << 4);
        *(uint4*)(smem + L_OFF_BH + sw) = *(const uint4*)(wh + off);
        *(uint4*)(smem + L_OFF_BL + sw) = *(const uint4*)(wl + off);
    }
    __syncthreads();

    uint32_t RA[4]; int rxa[4];
    const int u_a = (lane >> 4) & 1;
    #pragma unroll
    for (int mt = 0; mt < 4; mt++) {
        int row = warp_m*64 + mt*16 + (lane & 15);
        RA[mt] = sb + L_OFF_AH + row*128;
        rxa[mt] = row & 7;
    }
    uint32_t RB[2]; int rxb[2];
    const int u_b = (lane >> 3) & 1;
    #pragma unroll
    for (int p = 0; p < 2; p++) {
        int ch = warp_n*32 + p*16 + ((lane & 16) >> 1) + (lane & 7);
        RB[p] = sb + L_OFF_BH + ch*128;
        rxb[p] = ch & 7;
    }

    float acc[4][4][4];
    #pragma unroll
    for (int mt = 0; mt < 4; mt++)
        #pragma unroll
        for (int nt = 0; nt < 4; nt++)
            #pragma unroll
            for (int r4 = 0; r4 < 4; r4++) acc[mt][nt][r4] = 0.f;

    #pragma unroll
    for (int ks = 0; ks < 4; ks++) {
        uint32_t ah[4][4], al[4][4], bh[2][4], bl[2][4];
        #pragma unroll
        for (int mt = 0; mt < 4; mt++) {
            uint32_t off = (uint32_t)(((ks*2 + u_a) ^ rxa[mt]) << 4);
            ldsm4(ah[mt], RA[mt] + off);
            ldsm4(al[mt], RA[mt] + 16384 + off);
        }
        #pragma unroll
        for (int p = 0; p < 2; p++) {
            uint32_t off = (uint32_t)(((ks*2 + u_b) ^ rxb[p]) << 4);
            ldsm4(bh[p], RB[p] + off);
            ldsm4(bl[p], RB[p] + 16384 + off);
        }
        #pragma unroll
        for (int mt = 0; mt < 4; mt++)
            #pragma unroll
            for (int nt = 0; nt < 4; nt++) {
                int p = nt >> 1, ix = (nt & 1) * 2;
                mma16816(acc[mt][nt], ah[mt], bh[p][ix], bh[p][ix+1]);
                mma16816(acc[mt][nt], al[mt], bh[p][ix], bh[p][ix+1]);
                mma16816(acc[mt][nt], ah[mt], bl[p][ix], bl[p][ix+1]);
            }
    }
    __syncthreads();

    float* vsm = (float*)smem;
    #pragma unroll
    for (int mt = 0; mt < 4; mt++)
        #pragma unroll
        for (int nt = 0; nt < 4; nt++)
            #pragma unroll
            for (int r4 = 0; r4 < 4; r4++) {
                int row = warp_m*64 + mt*16 + grp + ((r4 & 2) ? 8 : 0);
                int col = warp_n*32 + nt*8 + 2*tig + (r4 & 1);
                vsm[col*133 + row] = acc[mt][nt][r4];
            }
    __syncthreads();

    {
        int c = tid & 127, halfp = tid >> 7;
        int idx = c0 + c;
        bool isP = (idx < COUT);
        int ch = isP ? idx : idx - COUT;
        float* gout = isP ? pDst : dDst;
        float sn = 0.f, sn2 = 0.f;
        const float* vc = vsm + c*133 + halfp*64;
        int bn0 = blockIdx.x*32 + halfp*16;
        #pragma unroll
        for (int i = 0; i < 16; i++) {
            float v0 = vc[i*4 + 0], v1 = vc[i*4 + 1], v2 = vc[i*4 + 2];
            size_t row = (size_t)(bn0 + i) * 3;
            gout[(row + 0)*COUT + ch] = v0;
            gout[(row + 1)*COUT + ch] = v1;
            gout[(row + 2)*COUT + ch] = v2;
            if (isP) {
                float q  = v0*v0 + v1*v1 + v2*v2;
                sn += sqrtf(q) + VEPS; sn2 += q;
            }
        }
        if (isP) {
            atomicAdd(&ssum[ch & 127], sn);
            atomicAdd(&ssum[128 + (ch & 127)], sn2);
        }
    }
    __syncthreads();
    if (c0 == 0 && tid < COUT) {
        atomicAdd(&sums[tid],        (double)ssum[tid & 127]);
        atomicAdd(&sums[COUT + tid], (double)ssum[128 + (tid & 127)]);
    }
}

// --------------------------- apply4: BN + VN-leaky -> g_h16 (fp16) ----------
__global__ __launch_bounds__(256) void apply4_kernel(const float* __restrict__ ga,
                                                     const float* __restrict__ be) {
    const int COUT = 128;
    int i = blockIdx.x * 256 + threadIdx.x;
    if (i >= BN * COUT) return;
    int bn = i / COUT, c = i % COUT;
    const double cnt = (double)BN;
    double mud = g_s4[c] / cnt;
    float  mu  = (float)mud;
    float  rs  = rsqrtf((float)(g_s4[COUT + c] / cnt - mud*mud) + BNEPS);
    size_t r = (size_t)bn * 3;
    float p0 = g_p[(r+0)*COUT + c], p1 = g_p[(r+1)*COUT + c], p2 = g_p[(r+2)*COUT + c];
    float q  = p0*p0 + p1*p1 + p2*p2;
    float inv = rsqrtf(fmaxf(q, 1e-30f));
    float nr = q*inv + VEPS;
    float sc = (ga[c]*(nr - mu)*rs + be[c]) * inv;
    p0 *= sc; p1 *= sc; p2 *= sc;
    float d0 = g_d[(r+0)*COUT + c], d1 = g_d[(r+1)*COUT + c], d2 = g_d[(r+2)*COUT + c];
    float dot = p0*d0 + p1*d1 + p2*d2;
    if (dot < 0.f) {
        float s2 = __fdividef(dot, d0*d0 + d1*d1 + d2*d2 + VEPS);
        p0 -= s2*d0; p1 -= s2*d1; p2 -= s2*d2;
    }
    size_t ro = (size_t)bn * 4;
    g_h16[(ro+0)*COUT + c] = __float2half_rn(p0);
    g_h16[(ro+1)*COUT + c] = __float2half_rn(p1);
    g_h16[(ro+2)*COUT + c] = __float2half_rn(p2);
    g_h16[(ro+3)*COUT + c] = __float2half_rn(0.f);
}

// --------------------------- conv5: fp16 mma.sync (R13 shape) ----------------
#define C5_OFF_A   0
#define C5_OFF_BH  32768
#define C5_OFF_BL  65536
#define C5_OFF_ACC 98304
#define C5_SMEM    102400

__device__ __forceinline__ int c5_swz(int row, int b8) {   // b8: byte off in 256B row
    return (row << 8) + (b8 ^ (((row & 3) << 5) | ((row & 4) << 2)));
}

__global__ __launch_bounds__(256, 2) void conv5_hmma() {
    extern __shared__ char smem[];
    const uint32_t sb = smem_u32(smem);
    float* accf = (float*)(smem + C5_OFF_ACC);

    const int tid  = threadIdx.x;
    const int lane = tid & 31, warp = tid >> 5;
    const int grp  = lane >> 2, tig = lane & 3;
    const int warp_m = warp >> 2, warp_n = warp & 3;
    const int m0 = blockIdx.x * 128;
    const int c0 = blockIdx.y * 128;

    for (int i = tid; i < 1024; i += 256) accf[i] = 0.f;

    #pragma unroll
    for (int i = 0; i < 16; i++) {
        int e = tid + i*256, r = e >> 5, q = e & 31;
        uint2 hv = *(const uint2*)(g_h16 + (size_t)(m0 + r)*128 + q*4);
        *(uint2*)(smem + C5_OFF_A + c5_swz(r, q*8)) = hv;
    }
    #pragma unroll
    for (int i = 0; i < 16; i++) {
        int e = tid + i*256, r = e >> 5, q = e & 31;
        size_t off = (size_t)(c0 + r)*128 + q*4;
        int sw = c5_swz(r, q*8);
        *(uint2*)(smem + C5_OFF_BH + sw) = *(const uint2*)(g_w5h + off);
        *(uint2*)(smem + C5_OFF_BL + sw) = *(const uint2*)(g_w5l + off);
    }
    __syncthreads();

    uint32_t PA[4], XA[4];
    #pragma unroll
    for (int mt = 0; mt < 4; mt++) {
        int row = warp_m*64 + mt*16 + (lane & 15);
        XA[mt] = (row & 3) << 5;
        PA[mt] = sb + C5_OFF_A + row*256 + ((lane & 16) ^ ((row & 4) << 2));
    }
    uint32_t PBh[2], PBl[2], XB[2];
    #pragma unroll
    for (int p = 0; p < 2; p++) {
        int ch = warp_n*32 + p*16 + ((lane & 16) >> 1) + (lane & 7);
        XB[p]  = (ch & 3) << 5;
        uint32_t off = ch*256 + (((lane & 8) << 1) ^ ((ch & 4) << 2));
        PBh[p] = sb + C5_OFF_BH + off;
        PBl[p] = sb + C5_OFF_BL + off;
    }

    float acc[4][4][4];
    #pragma unroll
    for (int mt = 0; mt < 4; mt++)
        #pragma unroll
        for (int nt = 0; nt < 4; nt++)
            #pragma unroll
            for (int r4 = 0; r4 < 4; r4++) acc[mt][nt][r4] = 0.f;

    #pragma unroll
    for (int ks = 0; ks < 8; ks++) {
        uint32_t a[4][4], bh[2][4], bl[2][4];
        #pragma unroll
        for (int mt = 0; mt < 4; mt++) ldsm4(a[mt], PA[mt] + ((ks*32) ^ XA[mt]));
        #pragma unroll
        for (int p = 0; p < 2; p++) {
            ldsm4(bh[p], PBh[p] + ((ks*32) ^ XB[p]));
            ldsm4(bl[p], PBl[p] + ((ks*32) ^ XB[p]));
        }
        #pragma unroll
        for (int mt = 0; mt < 4; mt++)
            #pragma unroll
            for (int nt = 0; nt < 4; nt++) {
                int p = nt >> 1, ix = (nt & 1) * 2;
                mma16816(acc[mt][nt], a[mt], bh[p][ix], bh[p][ix+1]);
                mma16816(acc[mt][nt], a[mt], bl[p][ix], bl[p][ix+1]);
            }
    }
    __syncthreads();

    float* vsm = (float*)smem;
    #pragma unroll
    for (int mt = 0; mt < 4; mt++)
        #pragma unroll
        for (int nt = 0; nt < 4; nt++)
            #pragma unroll
            for (int r4 = 0; r4 < 4; r4++) {
                int row = warp_m*64 + mt*16 + grp + ((r4 & 2) ? 8 : 0);
                int col = warp_n*32 + nt*8 + 2*tig + (r4 & 1);
                vsm[col*133 + row] = acc[mt][nt][r4];
            }
    __syncthreads();

    {
        int c = tid & 127, halfp = tid >> 7;
        float sn = 0.f, sn2 = 0.f;
        float sv0 = 0.f, sv1 = 0.f, sv2 = 0.f;
        float sw0 = 0.f, sw1 = 0.f, sw2 = 0.f;
        const float* vc = vsm + c*133 + halfp*64;
        #pragma unroll
        for (int i = 0; i < 16; i++) {
            float v0 = vc[i*4 + 0], v1 = vc[i*4 + 1], v2 = vc[i*4 + 2];
            float q  = v0*v0 + v1*v1 + v2*v2;
            float inv = rsqrtf(fmaxf(q, 1e-30f));
            float nr = q*inv + VEPS;
            sn += nr; sn2 += q;
            sv0 += v0; sv1 += v1; sv2 += v2;
            sw0 += v0*inv; sw1 += v1*inv; sw2 += v2*inv;
        }
        atomicAdd(&accf[c*8 + 0], sn);
        atomicAdd(&accf[c*8 + 1], sn2);
        atomicAdd(&accf[c*8 + 2], sv0);
        atomicAdd(&accf[c*8 + 3], sv1);
        atomicAdd(&accf[c*8 + 4], sv2);
        atomicAdd(&accf[c*8 + 5], sw0);
        atomicAdd(&accf[c*8 + 6], sw1);
        atomicAdd(&accf[c*8 + 7], sw2);
    }
    __syncthreads();

    const int b = blockIdx.x / 128;
    for (int i = tid; i < 1024; i += 256) {
        int c = i >> 3, q = i & 7;
        float vv = accf[i];
        int cg = c0 + c;
        if (q == 0)      atomicAdd(&g_s5[cg],        (double)vv);
        else if (q == 1) atomicAdd(&g_s5[1024 + cg], (double)vv);
        else if (q < 5)  atomicAdd(&g_sumv [(b*1024 + cg)*3 + (q-2)], vv);
        else             atomicAdd(&g_sumvn[(b*1024 + cg)*3 + (q-5)], vv);
    }
}

// --------------------------- final output ------------------------------------
__global__ void final_out(const float* __restrict__ g5, const float* __restrict__ b5,
                          float* __restrict__ out) {
    int c = blockIdx.x * 256 + threadIdx.x;
    if (c >= 1024) return;
    double mu  = g_s5[c]        / (double)BN;
    double var = g_s5[1024 + c] / (double)BN - mu*mu;
    float rs  = (float)(1.0 / sqrt(var + (double)BNEPS));
    float a   = g5[c] * rs;
    float t   = a * (float)mu - b5[c];
    #pragma unroll
    for (int b = 0; b < Bc; b++)
        #pragma unroll
        for (int comp = 0; comp < 3; comp++) {
            int gi = (b*1024 + c)*3 + comp;
            out[gi] = a * (g_sumv[gi] * (1.f/(float)Nc))
                    - t * (g_sumvn[gi] * (1.f/(float)Nc));
        }
}

// ---------------------------------------------------------------------------
extern "C" void kernel_launch(void* const* d_in, const int* in_sizes, int n_in,
                              void* d_out, int out_size) {
    const float* x  = (const float*)d_in[0];
    const float* W1 = (const float*)d_in[1];
    const float* D1 = (const float*)d_in[2];
    const float* g1 = (const float*)d_in[3];
    const float* b1 = (const float*)d_in[4];
    const float* W2 = (const float*)d_in[5];
    const float* D2 = (const float*)d_in[6];
    const float* g2 = (const float*)d_in[7];
    const float* b2 = (const float*)d_in[8];
    const float* W3 = (const float*)d_in[9];
    const float* D3 = (const float*)d_in[10];
    const float* g3 = (const float*)d_in[11];
    const float* b3 = (const float*)d_in[12];
    const float* W4 = (const float*)d_in[13];
    const float* D4 = (const float*)d_in[14];
    const float* g4 = (const float*)d_in[15];
    const float* b4 = (const float*)d_in[16];
    const float* W5 = (const float*)d_in[17];
    const float* g5 = (const float*)d_in[18];
    const float* b5 = (const float*)d_in[19];
    float* out = (float*)d_out;

    cudaFuncSetAttribute(knn_kernel, cudaFuncAttributeMaxDynamicSharedMemorySize, KNN_SMEM);
    cudaFuncSetAttribute(conv5_hmma, cudaFuncAttributeMaxDynamicSharedMemorySize, C5_SMEM);
    cudaFuncSetAttribute(gemm_hmma<64, 2, 0>,  cudaFuncAttributeMaxDynamicSharedMemorySize, L_SMEM);
    cudaFuncSetAttribute(gemm_hmma<64, 3, 1>,  cudaFuncAttributeMaxDynamicSharedMemorySize, L_SMEM);
    cudaFuncSetAttribute(gemm_hmma<128, 4, 1>, cudaFuncAttributeMaxDynamicSharedMemorySize, L_SMEM);

    prep_kernel<<<512, 256>>>(W2, D2, W3, D3, W4, D4, W5);  // my idx 0
    knn_kernel<<<dim3(Nc/32, Bc), 1024, KNN_SMEM>>>(x);     // my idx 1

    block1_stats<<<dim3(Nc/2, Bc), 128>>>(x, W1);           // my idx 2
    block1_apply<<<dim3(Nc/2, Bc), 128>>>(x, W1, D1, g1, b1);  // my idx 3 == profiled

    gemm_hmma<64, 2, 0><<<dim3(512, 1), 256, L_SMEM>>>(nullptr, nullptr);
    gemm_hmma<64, 3, 1><<<dim3(512, 1), 256, L_SMEM>>>(g2, b2);
    gemm_hmma<128, 4, 1><<<dim3(512, 2), 256, L_SMEM>>>(g3, b3);
    apply4_kernel<<<(BN*128 + 255)/256, 256>>>(g4, b4);

    conv5_hmma<<<dim3(65536/128, 1024/128), 256, C5_SMEM>>>();
    final_out<<<4, 256>>>(g5, b5, out);
}

// round 17
// speedup vs baseline: 1.1111x; 1.0011x over previous
#include <cuda_runtime.h>
#include <cuda_fp16.h>
#include <math.h>
#include <stdint.h>

#define Bc   4
#define Nc   4096
#define Kc   20
#define BN   (Bc*Nc)          // 16384
#define VEPS 1e-6f
#define BNEPS 1e-5f

// ---------------- persistent device scratch (no allocations allowed) -------
__device__ int    g_idx[Bc*Nc*Kc];
__device__ __half g_hAh[BN*4*64], g_hAl[BN*4*64];   // block1 output (hi/lo)
__device__ __half g_h16[BN*4*128];                  // fp16 h4 for conv5
__device__ float  g_p [BN*3*128];                   // p/d set A (layers 2,4)
__device__ float  g_d [BN*3*128];
__device__ float  g_pB[BN*3*64];                    // p/d set B (layer 3)
__device__ float  g_dB[BN*3*64];
__device__ double g_s1[128];
__device__ double g_s2[128];
__device__ double g_s3[128];
__device__ double g_s4[256];
__device__ double g_s5[2048];
__device__ float  g_sumv [Bc*1024*3];
__device__ float  g_sumvn[Bc*1024*3];
// pre-split weights
__device__ __half g_wd2h[128*64], g_wd2l[128*64];   // [W2;D2]
__device__ __half g_wd3h[128*64], g_wd3l[128*64];   // [W3;D3]
__device__ __half g_wd4h[256*64], g_wd4l[256*64];   // [W4;D4]
__device__ __half g_w5h[1024*128], g_w5l[1024*128];

// --------------------------- prep: zero stats + split weights ---------------
__global__ void prep_kernel(const float* __restrict__ W2, const float* __restrict__ D2,
                            const float* __restrict__ W3, const float* __restrict__ D3,
                            const float* __restrict__ W4, const float* __restrict__ D4,
                            const float* __restrict__ W5) {
    int i = blockIdx.x * 256 + threadIdx.x;          // grid 512*256 = 131072
    if (i < 128) { g_s1[i] = 0.0; g_s2[i] = 0.0; g_s3[i] = 0.0; }
    if (i < 256) { g_s4[i] = 0.0; }
    if (i < 2048){ g_s5[i] = 0.0; }
    if (i < Bc*1024*3) { g_sumv[i] = 0.f; g_sumvn[i] = 0.f; }
    {
        float v = W5[i];
        __half h = __float2half_rn(v);
        g_w5h[i] = h;
        g_w5l[i] = __float2half_rn(v - __half2float(h));
    }
    if (i < 16384) {
        int row = i >> 6, col = i & 63;
        float v = (row < 128) ? W4[row*64 + col] : D4[(row-128)*64 + col];
        __half h = __float2half_rn(v);
        g_wd4h[i] = h;
        g_wd4l[i] = __float2half_rn(v - __half2float(h));
    }
    if (i < 8192) {
        int row = i >> 6, col = i & 63;
        float v2 = (row < 64) ? W2[row*64 + col] : D2[(row-64)*64 + col];
        __half h2 = __float2half_rn(v2);
        g_wd2h[i] = h2;
        g_wd2l[i] = __float2half_rn(v2 - __half2float(h2));
        float v3 = (row < 64) ? W3[row*64 + col] : D3[(row-64)*64 + col];
        __half h3 = __float2half_rn(v3);
        g_wd3h[i] = h3;
        g_wd3l[i] = __float2half_rn(v3 - __half2float(h3));
    }
}

// ===================== mma/ldmatrix helpers ==================================
__device__ __forceinline__ uint32_t smem_u32(const void* p) {
    uint32_t a;
    asm("{ .reg .u64 t; cvta.to.shared.u64 t, %1; cvt.u32.u64 %0, t; }" : "=r"(a) : "l"(p));
    return a;
}
__device__ __forceinline__ void ldsm4(uint32_t* r, uint32_t addr) {
    asm volatile("ldmatrix.sync.aligned.m8n8.x4.shared.b16 {%0,%1,%2,%3}, [%4];"
        : "=r"(r[0]), "=r"(r[1]), "=r"(r[2]), "=r"(r[3]) : "r"(addr));
}
__device__ __forceinline__ void mma16816(float* c, const uint32_t* a, uint32_t b0, uint32_t b1) {
    asm volatile("mma.sync.aligned.m16n8k16.row.col.f32.f16.f16.f32 "
        "{%0,%1,%2,%3}, {%4,%5,%6,%7}, {%8,%9}, {%0,%1,%2,%3};"
        : "+f"(c[0]), "+f"(c[1]), "+f"(c[2]), "+f"(c[3])
        : "r"(a[0]), "r"(a[1]), "r"(a[2]), "r"(a[3]), "r"(b0), "r"(b1));
}
__device__ __forceinline__ uint32_t packh2f(float lo, float hi) {
    uint32_t r; asm("cvt.rn.f16x2.f32 %0, %1, %2;" : "=r"(r) : "f"(hi), "f"(lo)); return r;
}

// --------------------------- KNN: float4 score scan + redux argmax ----------
#define KNN_SMEM (Nc*16)                 // 65536 bytes

__device__ __forceinline__ uint32_t fkey(float f) {
    uint32_t b = __float_as_uint(f);
    return b ^ (uint32_t)(((int32_t)b >> 31) | 0x80000000);
}

__global__ __launch_bounds__(1024) void knn_kernel(const float* __restrict__ x) {
    extern __shared__ float4 pts[];

    const int tid = threadIdx.x;
    const int b = blockIdx.y;
    const float4* xb4 = (const float4*)(x + (size_t)b * Nc * 3);

    {
        float4 v0 = xb4[tid*3 + 0];
        float4 v1 = xb4[tid*3 + 1];
        float4 v2 = xb4[tid*3 + 2];
        int p = tid * 4;
        pts[p+0] = make_float4(v0.x, v0.y, v0.z, -(v0.x*v0.x + v0.y*v0.y + v0.z*v0.z));
        pts[p+1] = make_float4(v0.w, v1.x, v1.y, -(v0.w*v0.w + v1.x*v1.x + v1.y*v1.y));
        pts[p+2] = make_float4(v1.z, v1.w, v2.x, -(v1.z*v1.z + v1.w*v1.w + v2.x*v2.x));
        pts[p+3] = make_float4(v2.y, v2.z, v2.w, -(v2.y*v2.y + v2.z*v2.z + v2.w*v2.w));
    }
    __syncthreads();

    const int w = tid >> 5, lane = tid & 31;
    const int n = blockIdx.x * 32 + w;

    const float4 q = pts[n];
    const float qx2 = 2.f*q.x, qy2 = 2.f*q.y, qz2 = 2.f*q.z;

    uint32_t mk[4]; uint32_t mi4[4];
    uint32_t msk[4] = {0u, 0u, 0u, 0u};

    // init: even/odd split compare chains (each ascending -> lowest idx on tie;
    // merge with explicit idx tie-break -> exact argmax w/ lowest index)
    #pragma unroll
    for (int c = 0; c < 4; c++) {
        float cmA = -3.4e38f, cmB = -3.4e38f;
        int cjA = 0, cjB = 0;
        #pragma unroll 8
        for (int i = 0; i < 32; i += 2) {
            int jA = lane + ((c*32 + i) << 5);
            int jB = jA + 32;
            float4 a = pts[jA];
            float4 bb = pts[jB];
            float dA = fmaf(a.x,  qx2, fmaf(a.y,  qy2, fmaf(a.z,  qz2, a.w)));
            float dB = fmaf(bb.x, qx2, fmaf(bb.y, qy2, fmaf(bb.z, qz2, bb.w)));
            if (dA > cmA) { cmA = dA; cjA = jA; }
            if (dB > cmB) { cmB = dB; cjB = jB; }
        }
        if (cmB > cmA || (cmB == cmA && cjB < cjA)) { cmA = cmB; cjA = cjB; }
        mk[c] = fkey(cmA); mi4[c] = (uint32_t)cjA;
    }
    uint32_t bk = mk[0], bj = mi4[0];
    #pragma unroll
    for (int c = 1; c < 4; c++)
        if (mk[c] > bk || (mk[c] == bk && mi4[c] < bj)) { bk = mk[c]; bj = mi4[c]; }

    for (int k = 0; k < Kc; k++) {
        uint32_t best = __reduce_max_sync(0xffffffffu, bk);
        uint32_t cand = (bk == best) ? bj : 0xffffffffu;
        uint32_t j = __reduce_min_sync(0xffffffffu, cand);
        if (lane == 0) g_idx[((size_t)b*Nc + n)*Kc + k] = (int)j;
        if (k == Kc - 1) break;

        const int wl = (int)(j & 31);
        const int C  = (int)(j >> 10);
        const int ib = (int)((j >> 5) & 31);
        if (lane == wl) {
            if (C == 0) msk[0] |= 1u << ib;
            else if (C == 1) msk[1] |= 1u << ib;
            else if (C == 2) msk[2] |= 1u << ib;
            else msk[3] |= 1u << ib;
        }
        uint32_t myb = (C == 0) ? msk[0] : (C == 1) ? msk[1]
                     : (C == 2) ? msk[2] : msk[3];
        uint32_t bm = __shfl_sync(0xffffffffu, myb, wl);

        int jj = wl + ((C*32 + lane) << 5);
        float4 a = pts[jj];
        float d = fmaf(a.x, qx2, fmaf(a.y, qy2, fmaf(a.z, qz2, a.w)));
        uint32_t ck = ((bm >> lane) & 1u) ? 0u : fkey(d);
        uint32_t best2 = __reduce_max_sync(0xffffffffu, ck);
        uint32_t cand2 = (ck == best2 && ck != 0u) ? (uint32_t)jj : 0xffffffffu;
        uint32_t j2 = __reduce_min_sync(0xffffffffu, cand2);

        if (lane == wl) {
            if (C == 0)      { mk[0] = best2; mi4[0] = j2; }
            else if (C == 1) { mk[1] = best2; mi4[1] = j2; }
            else if (C == 2) { mk[2] = best2; mi4[2] = j2; }
            else             { mk[3] = best2; mi4[3] = j2; }
            bk = mk[0]; bj = mi4[0];
            #pragma unroll
            for (int c = 1; c < 4; c++)
                if (mk[c] > bk || (mk[c] == bk && mi4[c] < bj)) { bk = mk[c]; bj = mi4[c]; }
        }
    }
}

// --------------------------- block1 (3ch edge feat -> 64) -------------------
__device__ __forceinline__ void build_f(const float* __restrict__ x, int b, int n0,
                                        float f[2][Kc][9]) {
    int t = threadIdx.x;
    if (t < 2*Kc) {
        int ln = t / Kc, k = t % Kc;
        int n = n0 + ln;
        const float* xb = x + (size_t)b * Nc * 3;
        float cx = xb[n*3+0], cy = xb[n*3+1], cz = xb[n*3+2];
        int j = g_idx[((size_t)b*Nc + n)*Kc + k];
        float ax = xb[j*3+0], ay = xb[j*3+1], az = xb[j*3+2];
        f[ln][k][0] = ax - cx; f[ln][k][1] = ay - cy; f[ln][k][2] = az - cz;
        f[ln][k][3] = cx;      f[ln][k][4] = cy;      f[ln][k][5] = cz;
        f[ln][k][6] = ay*cz - az*cy;
        f[ln][k][7] = az*cx - ax*cz;
        f[ln][k][8] = ax*cy - ay*cx;
    }
}

__global__ __launch_bounds__(128) void block1_stats(const float* __restrict__ x,
                                                    const float* __restrict__ W1) {
    int b = blockIdx.y, n0 = blockIdx.x * 2;
    __shared__ float f[2][Kc][9];
    __shared__ float red[2][128];
    build_f(x, b, n0, f);
    __syncthreads();
    int t = threadIdx.x;
    int ln = t >> 6, c = t & 63;
    float w0 = W1[c*3+0], w1 = W1[c*3+1], w2 = W1[c*3+2];
    float sn = 0.f, sn2 = 0.f;
    #pragma unroll
    for (int k = 0; k < Kc; k++) {
        const float* fk = f[ln][k];
        float p0 = w0*fk[0] + w1*fk[3] + w2*fk[6];
        float p1 = w0*fk[1] + w1*fk[4] + w2*fk[7];
        float p2 = w0*fk[2] + w1*fk[5] + w2*fk[8];
        float nr = sqrtf(p0*p0 + p1*p1 + p2*p2) + VEPS;
        sn += nr; sn2 += nr*nr;
    }
    red[ln][c] = sn; red[ln][64 + c] = sn2;
    __syncthreads();
    if (t < 64) {
        atomicAdd(&g_s1[t],      (double)red[0][t]      + (double)red[1][t]);
        atomicAdd(&g_s1[64 + t], (double)red[0][64 + t] + (double)red[1][64 + t]);
    }
}

__global__ __launch_bounds__(128) void block1_apply(const float* __restrict__ x,
                                                    const float* __restrict__ W1,
                                                    const float* __restrict__ D1,
                                                    const float* __restrict__ g1,
                                                    const float* __restrict__ b1) {
    int b = blockIdx.y, n0 = blockIdx.x * 2;
    __shared__ float f[2][Kc][9];
    build_f(x, b, n0, f);
    __syncthreads();
    int t = threadIdx.x;
    int ln = t >> 6, c = t & 63;
    float w0 = W1[c*3+0], w1 = W1[c*3+1], w2 = W1[c*3+2];
    float e0 = D1[c*3+0], e1 = D1[c*3+1], e2 = D1[c*3+2];
    const double cnt = (double)(Bc*Nc*Kc);
    double mud = g_s1[c] / cnt;
    float  mu  = (float)mud;
    float  rs  = rsqrtf((float)(g_s1[64 + c] / cnt - mud*mud) + BNEPS);
    float ga = g1[c], be = b1[c];
    float a0 = 0.f, a1 = 0.f, a2 = 0.f;
    #pragma unroll
    for (int k = 0; k < Kc; k++) {
        const float* fk = f[ln][k];
        float p0 = w0*fk[0] + w1*fk[3] + w2*fk[6];
        float p1 = w0*fk[1] + w1*fk[4] + w2*fk[7];
        float p2 = w0*fk[2] + w1*fk[5] + w2*fk[8];
        float q  = p0*p0 + p1*p1 + p2*p2;
        float inv = rsqrtf(fmaxf(q, 1e-30f));
        float nr = q*inv + VEPS;
        float sc = (ga*(nr - mu)*rs + be) * inv;
        p0 *= sc; p1 *= sc; p2 *= sc;
        float d0 = e0*fk[0] + e1*fk[3] + e2*fk[6];
        float d1 = e0*fk[1] + e1*fk[4] + e2*fk[7];
        float d2 = e0*fk[2] + e1*fk[5] + e2*fk[8];
        float dot = p0*d0 + p1*d1 + p2*d2;
        if (dot < 0.f) {
            float s2 = __fdividef(dot, d0*d0 + d1*d1 + d2*d2 + VEPS);
            p0 -= s2*d0; p1 -= s2*d1; p2 -= s2*d2;
        }
        a0 += p0; a1 += p1; a2 += p2;
    }
    size_t bn = (size_t)b*Nc + n0 + ln;
    const float inv = 1.f / (float)Kc;
    float v[3] = {a0*inv, a1*inv, a2*inv};
    #pragma unroll
    for (int comp = 0; comp < 3; comp++) {
        __half hv = __float2half_rn(v[comp]);
        g_hAh[(bn*4 + comp)*64 + c] = hv;
        g_hAl[(bn*4 + comp)*64 + c] = __float2half_rn(v[comp] - __half2float(hv));
    }
    g_hAh[(bn*4 + 3)*64 + c] = __float2half_rn(0.f);
    g_hAl[(bn*4 + 3)*64 + c] = __float2half_rn(0.f);
}

// --------------------------- layers 2-4: HMMA GEMM + fused apply staging ----
#define L_OFF_AH 0
#define L_OFF_AL 16384
#define L_OFF_BH 32768
#define L_OFF_BL 49152
#define L_OFF_SS 68096                   // ssum: 256 floats
#define L_OFF_PM 69120                   // mu/rstd/ga/be: 4*64 floats
#define L_SMEM   70144

template<int COUT, int WHICH, int APPLY>
__global__ __launch_bounds__(256, 2) void gemm_hmma(const float* __restrict__ gaPrev,
                                                    const float* __restrict__ bePrev) {
    extern __shared__ char smem[];
    const uint32_t sb = smem_u32(smem);
    const int tid  = threadIdx.x;
    const int lane = tid & 31, warp = tid >> 5;
    const int grp  = lane >> 2, tig = lane & 3;
    const int warp_m = warp >> 2, warp_n = warp & 3;
    const int m0 = blockIdx.x * 128;
    const int c0 = blockIdx.y * 128;
    const __half* __restrict__ wh = (WHICH == 2) ? g_wd2h : (WHICH == 3) ? g_wd3h : g_wd4h;
    const __half* __restrict__ wl = (WHICH == 2) ? g_wd2l : (WHICH == 3) ? g_wd3l : g_wd4l;
    double* sums = (WHICH == 2) ? g_s2 : (WHICH == 3) ? g_s3 : g_s4;
    const float* __restrict__ pSrc = (WHICH == 3) ? g_p  : g_pB;
    const float* __restrict__ dSrc = (WHICH == 3) ? g_d  : g_dB;
    const double* sPrev = (WHICH == 3) ? g_s2 : g_s3;
    float* pDst = (WHICH == 3) ? g_pB : g_p;
    float* dDst = (WHICH == 3) ? g_dB : g_d;

    float* ssum = (float*)(smem + L_OFF_SS);
    ssum[tid] = 0.f;

    if (APPLY) {
        float* prm = (float*)(smem + L_OFF_PM);   // mu[64], rstd[64], ga[64], be[64]
        if (tid < 64) {
            double mud = sPrev[tid] / (double)BN;
            prm[tid]       = (float)mud;
            prm[64 + tid]  = rsqrtf((float)(sPrev[64 + tid] / (double)BN - mud*mud) + BNEPS);
            prm[128 + tid] = gaPrev[tid];
            prm[192 + tid] = bePrev[tid];
        }
        __syncthreads();
        const int pt = tid >> 3, cg = tid & 7;
        const size_t ptg = (size_t)(blockIdx.x*32 + pt);
        float p[3][8], d[3][8];
        #pragma unroll
        for (int comp = 0; comp < 3; comp++) {
            size_t off = (ptg*3 + comp)*64 + cg*8;
            *(float4*)&p[comp][0] = *(const float4*)(pSrc + off);
            *(float4*)&p[comp][4] = *(const float4*)(pSrc + off + 4);
            *(float4*)&d[comp][0] = *(const float4*)(dSrc + off);
            *(float4*)&d[comp][4] = *(const float4*)(dSrc + off + 4);
        }
        #pragma unroll
        for (int j = 0; j < 8; j++) {
            int c = cg*8 + j;
            float q  = p[0][j]*p[0][j] + p[1][j]*p[1][j] + p[2][j]*p[2][j];
            float iv = rsqrtf(fmaxf(q, 1e-30f));
            float nr = q*iv + VEPS;
            float sc = (prm[128+c]*(nr - prm[c])*prm[64+c] + prm[192+c]) * iv;
            float p0 = p[0][j]*sc, p1 = p[1][j]*sc, p2 = p[2][j]*sc;
            float dot = p0*d[0][j] + p1*d[1][j] + p2*d[2][j];
            if (dot < 0.f) {
                float s2 = __fdividef(dot, d[0][j]*d[0][j] + d[1][j]*d[1][j] + d[2][j]*d[2][j] + VEPS);
                p0 -= s2*d[0][j]; p1 -= s2*d[1][j]; p2 -= s2*d[2][j];
            }
            p[0][j] = p0; p[1][j] = p1; p[2][j] = p2;
        }
        #pragma unroll
        for (int comp = 0; comp < 4; comp++) {
            int row = pt*4 + comp;
            uint32_t sw = row*128 + ((cg ^ (row & 7)) << 4);
            uint4 hh, ll;
            if (comp < 3) {
                float h0 = __half2float(__float2half_rn(p[comp][0]));
                float h1 = __half2float(__float2half_rn(p[comp][1]));
                float h2 = __half2float(__float2half_rn(p[comp][2]));
                float h3 = __half2float(__float2half_rn(p[comp][3]));
                float h4 = __half2float(__float2half_rn(p[comp][4]));
                float h5 = __half2float(__float2half_rn(p[comp][5]));
                float h6 = __half2float(__float2half_rn(p[comp][6]));
                float h7 = __half2float(__float2half_rn(p[comp][7]));
                hh = make_uint4(packh2f(h0,h1), packh2f(h2,h3), packh2f(h4,h5), packh2f(h6,h7));
                ll = make_uint4(packh2f(p[comp][0]-h0, p[comp][1]-h1),
                                packh2f(p[comp][2]-h2, p[comp][3]-h3),
                                packh2f(p[comp][4]-h4, p[comp][5]-h5),
                                packh2f(p[comp][6]-h6, p[comp][7]-h7));
            } else {
                hh = make_uint4(0u, 0u, 0u, 0u);
                ll = make_uint4(0u, 0u, 0u, 0u);
            }
            *(uint4*)(smem + L_OFF_AH + sw) = hh;
            *(uint4*)(smem + L_OFF_AL + sw) = ll;
        }
    } else {
        #pragma unroll
        for (int i = 0; i < 4; i++) {
            int e = tid + i*256, r = e >> 3, un = e & 7;
            size_t off = (size_t)(m0 + r)*64 + un*8;
            uint32_t sw = r*128 + ((un ^ (r & 7)) << 4);
            *(uint4*)(smem + L_OFF_AH + sw) = *(const uint4*)(g_hAh + off);
            *(uint4*)(smem + L_OFF_AL + sw) = *(const uint4*)(g_hAl + off);
        }
    }
    #pragma unroll
    for (int i = 0; i < 4; i++) {
        int e = tid + i*256, r = e >> 3, un = e & 7;
        size_t off = (size_t)(c0 + r)*64 + un*8;
        uint32_t sw = r*128 + ((un ^ (r & 7)) << 4);
        *(uint4*)(smem + L_OFF_BH + sw) = *(const uint4*)(wh + off);
        *(uint4*)(smem + L_OFF_BL + sw) = *(const uint4*)(wl + off);
    }
    __syncthreads();

    uint32_t RA[4]; int rxa[4];
    const int u_a = (lane >> 4) & 1;
    #pragma unroll
    for (int mt = 0; mt < 4; mt++) {
        int row = warp_m*64 + mt*16 + (lane & 15);
        RA[mt] = sb + L_OFF_AH + row*128;
        rxa[mt] = row & 7;
    }
    uint32_t RB[2]; int rxb[2];
    const int u_b = (lane >> 3) & 1;
    #pragma unroll
    for (int p = 0; p < 2; p++) {
        int ch = warp_n*32 + p*16 + ((lane & 16) >> 1) + (lane & 7);
        RB[p] = sb + L_OFF_BH + ch*128;
        rxb[p] = ch & 7;
    }

    float acc[4][4][4];
    #pragma unroll
    for (int mt = 0; mt < 4; mt++)
        #pragma unroll
        for (int nt = 0; nt < 4; nt++)
            #pragma unroll
            for (int r4 = 0; r4 < 4; r4++) acc[mt][nt][r4] = 0.f;

    #pragma unroll
    for (int ks = 0; ks < 4; ks++) {
        uint32_t ah[4][4], al[4][4], bh[2][4], bl[2][4];
        #pragma unroll
        for (int mt = 0; mt < 4; mt++) {
            uint32_t off = (uint32_t)(((ks*2 + u_a) ^ rxa[mt]) << 4);
            ldsm4(ah[mt], RA[mt] + off);
            ldsm4(al[mt], RA[mt] + 16384 + off);
        }
        #pragma unroll
        for (int p = 0; p < 2; p++) {
            uint32_t off = (uint32_t)(((ks*2 + u_b) ^ rxb[p]) << 4);
            ldsm4(bh[p], RB[p] + off);
            ldsm4(bl[p], RB[p] + 16384 + off);
        }
        #pragma unroll
        for (int mt = 0; mt < 4; mt++)
            #pragma unroll
            for (int nt = 0; nt < 4; nt++) {
                int p = nt >> 1, ix = (nt & 1) * 2;
                mma16816(acc[mt][nt], ah[mt], bh[p][ix], bh[p][ix+1]);
                mma16816(acc[mt][nt], al[mt], bh[p][ix], bh[p][ix+1]);
                mma16816(acc[mt][nt], ah[mt], bl[p][ix], bl[p][ix+1]);
            }
    }
    __syncthreads();

    float* vsm = (float*)smem;
    #pragma unroll
    for (int mt = 0; mt < 4; mt++)
        #pragma unroll
        for (int nt = 0; nt < 4; nt++)
            #pragma unroll
            for (int r4 = 0; r4 < 4; r4++) {
                int row = warp_m*64 + mt*16 + grp + ((r4 & 2) ? 8 : 0);
                int col = warp_n*32 + nt*8 + 2*tig + (r4 & 1);
                vsm[col*133 + row] = acc[mt][nt][r4];
            }
    __syncthreads();

    {
        int c = tid & 127, halfp = tid >> 7;
        int idx = c0 + c;
        bool isP = (idx < COUT);
        int ch = isP ? idx : idx - COUT;
        float* gout = isP ? pDst : dDst;
        float sn = 0.f, sn2 = 0.f;
        const float* vc = vsm + c*133 + halfp*64;
        int bn0 = blockIdx.x*32 + halfp*16;
        #pragma unroll
        for (int i = 0; i < 16; i++) {
            float v0 = vc[i*4 + 0], v1 = vc[i*4 + 1], v2 = vc[i*4 + 2];
            size_t row = (size_t)(bn0 + i) * 3;
            gout[(row + 0)*COUT + ch] = v0;
            gout[(row + 1)*COUT + ch] = v1;
            gout[(row + 2)*COUT + ch] = v2;
            if (isP) {
                float q  = v0*v0 + v1*v1 + v2*v2;
                sn += sqrtf(q) + VEPS; sn2 += q;
            }
        }
        if (isP) {
            atomicAdd(&ssum[ch & 127], sn);
            atomicAdd(&ssum[128 + (ch & 127)], sn2);
        }
    }
    __syncthreads();
    if (c0 == 0 && tid < COUT) {
        atomicAdd(&sums[tid],        (double)ssum[tid & 127]);
        atomicAdd(&sums[COUT + tid], (double)ssum[128 + (tid & 127)]);
    }
}

// --------------------------- apply4: BN + VN-leaky -> g_h16 (fp16) ----------
__global__ __launch_bounds__(256) void apply4_kernel(const float* __restrict__ ga,
                                                     const float* __restrict__ be) {
    const int COUT = 128;
    int i = blockIdx.x * 256 + threadIdx.x;
    if (i >= BN * COUT) return;
    int bn = i / COUT, c = i % COUT;
    const double cnt = (double)BN;
    double mud = g_s4[c] / cnt;
    float  mu  = (float)mud;
    float  rs  = rsqrtf((float)(g_s4[COUT + c] / cnt - mud*mud) + BNEPS);
    size_t r = (size_t)bn * 3;
    float p0 = g_p[(r+0)*COUT + c], p1 = g_p[(r+1)*COUT + c], p2 = g_p[(r+2)*COUT + c];
    float q  = p0*p0 + p1*p1 + p2*p2;
    float inv = rsqrtf(fmaxf(q, 1e-30f));
    float nr = q*inv + VEPS;
    float sc = (ga[c]*(nr - mu)*rs + be[c]) * inv;
    p0 *= sc; p1 *= sc; p2 *= sc;
    float d0 = g_d[(r+0)*COUT + c], d1 = g_d[(r+1)*COUT + c], d2 = g_d[(r+2)*COUT + c];
    float dot = p0*d0 + p1*d1 + p2*d2;
    if (dot < 0.f) {
        float s2 = __fdividef(dot, d0*d0 + d1*d1 + d2*d2 + VEPS);
        p0 -= s2*d0; p1 -= s2*d1; p2 -= s2*d2;
    }
    size_t ro = (size_t)bn * 4;
    g_h16[(ro+0)*COUT + c] = __float2half_rn(p0);
    g_h16[(ro+1)*COUT + c] = __float2half_rn(p1);
    g_h16[(ro+2)*COUT + c] = __float2half_rn(p2);
    g_h16[(ro+3)*COUT + c] = __float2half_rn(0.f);
}

// --------------------------- conv5: fp16 mma.sync (R13 shape) ----------------
#define C5_OFF_A   0
#define C5_OFF_BH  32768
#define C5_OFF_BL  65536
#define C5_OFF_ACC 98304
#define C5_SMEM    102400

__device__ __forceinline__ int c5_swz(int row, int b8) {   // b8: byte off in 256B row
    return (row << 8) + (b8 ^ (((row & 3) << 5) | ((row & 4) << 2)));
}

__global__ __launch_bounds__(256, 2) void conv5_hmma() {
    extern __shared__ char smem[];
    const uint32_t sb = smem_u32(smem);
    float* accf = (float*)(smem + C5_OFF_ACC);

    const int tid  = threadIdx.x;
    const int lane = tid & 31, warp = tid >> 5;
    const int grp  = lane >> 2, tig = lane & 3;
    const int warp_m = warp >> 2, warp_n = warp & 3;
    const int m0 = blockIdx.x * 128;
    const int c0 = blockIdx.y * 128;

    for (int i = tid; i < 1024; i += 256) accf[i] = 0.f;

    #pragma unroll
    for (int i = 0; i < 16; i++) {
        int e = tid + i*256, r = e >> 5, q = e & 31;
        uint2 hv = *(const uint2*)(g_h16 + (size_t)(m0 + r)*128 + q*4);
        *(uint2*)(smem + C5_OFF_A + c5_swz(r, q*8)) = hv;
    }
    #pragma unroll
    for (int i = 0; i < 16; i++) {
        int e = tid + i*256, r = e >> 5, q = e & 31;
        size_t off = (size_t)(c0 + r)*128 + q*4;
        int sw = c5_swz(r, q*8);
        *(uint2*)(smem + C5_OFF_BH + sw) = *(const uint2*)(g_w5h + off);
        *(uint2*)(smem + C5_OFF_BL + sw) = *(const uint2*)(g_w5l + off);
    }
    __syncthreads();

    uint32_t PA[4], XA[4];
    #pragma unroll
    for (int mt = 0; mt < 4; mt++) {
        int row = warp_m*64 + mt*16 + (lane & 15);
        XA[mt] = (row & 3) << 5;
        PA[mt] = sb + C5_OFF_A + row*256 + ((lane & 16) ^ ((row & 4) << 2));
    }
    uint32_t PBh[2], PBl[2], XB[2];
    #pragma unroll
    for (int p = 0; p < 2; p++) {
        int ch = warp_n*32 + p*16 + ((lane & 16) >> 1) + (lane & 7);
        XB[p]  = (ch & 3) << 5;
        uint32_t off = ch*256 + (((lane & 8) << 1) ^ ((ch & 4) << 2));
        PBh[p] = sb + C5_OFF_BH + off;
        PBl[p] = sb + C5_OFF_BL + off;
    }

    float acc[4][4][4];
    #pragma unroll
    for (int mt = 0; mt < 4; mt++)
        #pragma unroll
        for (int nt = 0; nt < 4; nt++)
            #pragma unroll
            for (int r4 = 0; r4 < 4; r4++) acc[mt][nt][r4] = 0.f;

    #pragma unroll
    for (int ks = 0; ks < 8; ks++) {
        uint32_t a[4][4], bh[2][4], bl[2][4];
        #pragma unroll
        for (int mt = 0; mt < 4; mt++) ldsm4(a[mt], PA[mt] + ((ks*32) ^ XA[mt]));
        #pragma unroll
        for (int p = 0; p < 2; p++) {
            ldsm4(bh[p], PBh[p] + ((ks*32) ^ XB[p]));
            ldsm4(bl[p], PBl[p] + ((ks*32) ^ XB[p]));
        }
        #pragma unroll
        for (int mt = 0; mt < 4; mt++)
            #pragma unroll
            for (int nt = 0; nt < 4; nt++) {
                int p = nt >> 1, ix = (nt & 1) * 2;
                mma16816(acc[mt][nt], a[mt], bh[p][ix], bh[p][ix+1]);
                mma16816(acc[mt][nt], a[mt], bl[p][ix], bl[p][ix+1]);
            }
    }
    __syncthreads();

    float* vsm = (float*)smem;
    #pragma unroll
    for (int mt = 0; mt < 4; mt++)
        #pragma unroll
        for (int nt = 0; nt < 4; nt++)
            #pragma unroll
            for (int r4 = 0; r4 < 4; r4++) {
                int row = warp_m*64 + mt*16 + grp + ((r4 & 2) ? 8 : 0);
                int col = warp_n*32 + nt*8 + 2*tig + (r4 & 1);
                vsm[col*133 + row] = acc[mt][nt][r4];
            }
    __syncthreads();

    {
        int c = tid & 127, halfp = tid >> 7;
        float sn = 0.f, sn2 = 0.f;
        float sv0 = 0.f, sv1 = 0.f, sv2 = 0.f;
        float sw0 = 0.f, sw1 = 0.f, sw2 = 0.f;
        const float* vc = vsm + c*133 + halfp*64;
        #pragma unroll
        for (int i = 0; i < 16; i++) {
            float v0 = vc[i*4 + 0], v1 = vc[i*4 + 1], v2 = vc[i*4 + 2];
            float q  = v0*v0 + v1*v1 + v2*v2;
            float inv = rsqrtf(fmaxf(q, 1e-30f));
            float nr = q*inv + VEPS;
            sn += nr; sn2 += q;
            sv0 += v0; sv1 += v1; sv2 += v2;
            sw0 += v0*inv; sw1 += v1*inv; sw2 += v2*inv;
        }
        atomicAdd(&accf[c*8 + 0], sn);
        atomicAdd(&accf[c*8 + 1], sn2);
        atomicAdd(&accf[c*8 + 2], sv0);
        atomicAdd(&accf[c*8 + 3], sv1);
        atomicAdd(&accf[c*8 + 4], sv2);
        atomicAdd(&accf[c*8 + 5], sw0);
        atomicAdd(&accf[c*8 + 6], sw1);
        atomicAdd(&accf[c*8 + 7], sw2);
    }
    __syncthreads();

    const int b = blockIdx.x / 128;
    for (int i = tid; i < 1024; i += 256) {
        int c = i >> 3, q = i & 7;
        float vv = accf[i];
        int cg = c0 + c;
        if (q == 0)      atomicAdd(&g_s5[cg],        (double)vv);
        else if (q == 1) atomicAdd(&g_s5[1024 + cg], (double)vv);
        else if (q < 5)  atomicAdd(&g_sumv [(b*1024 + cg)*3 + (q-2)], vv);
        else             atomicAdd(&g_sumvn[(b*1024 + cg)*3 + (q-5)], vv);
    }
}

// --------------------------- final output ------------------------------------
__global__ void final_out(const float* __restrict__ g5, const float* __restrict__ b5,
                          float* __restrict__ out) {
    int c = blockIdx.x * 256 + threadIdx.x;
    if (c >= 1024) return;
    double mu  = g_s5[c]        / (double)BN;
    double var = g_s5[1024 + c] / (double)BN - mu*mu;
    float rs  = (float)(1.0 / sqrt(var + (double)BNEPS));
    float a   = g5[c] * rs;
    float t   = a * (float)mu - b5[c];
    #pragma unroll
    for (int b = 0; b < Bc; b++)
        #pragma unroll
        for (int comp = 0; comp < 3; comp++) {
            int gi = (b*1024 + c)*3 + comp;
            out[gi] = a * (g_sumv[gi] * (1.f/(float)Nc))
                    - t * (g_sumvn[gi] * (1.f/(float)Nc));
        }
}

// ---------------------------------------------------------------------------
extern "C" void kernel_launch(void* const* d_in, const int* in_sizes, int n_in,
                              void* d_out, int out_size) {
    const float* x  = (const float*)d_in[0];
    const float* W1 = (const float*)d_in[1];
    const float* D1 = (const float*)d_in[2];
    const float* g1 = (const float*)d_in[3];
    const float* b1 = (const float*)d_in[4];
    const float* W2 = (const float*)d_in[5];
    const float* D2 = (const float*)d_in[6];
    const float* g2 = (const float*)d_in[7];
    const float* b2 = (const float*)d_in[8];
    const float* W3 = (const float*)d_in[9];
    const float* D3 = (const float*)d_in[10];
    const float* g3 = (const float*)d_in[11];
    const float* b3 = (const float*)d_in[12];
    const float* W4 = (const float*)d_in[13];
    const float* D4 = (const float*)d_in[14];
    const float* g4 = (const float*)d_in[15];
    const float* b4 = (const float*)d_in[16];
    const float* W5 = (const float*)d_in[17];
    const float* g5 = (const float*)d_in[18];
    const float* b5 = (const float*)d_in[19];
    float* out = (float*)d_out;

    cudaFuncSetAttribute(knn_kernel, cudaFuncAttributeMaxDynamicSharedMemorySize, KNN_SMEM);
    cudaFuncSetAttribute(conv5_hmma, cudaFuncAttributeMaxDynamicSharedMemorySize, C5_SMEM);
    cudaFuncSetAttribute(gemm_hmma<64, 2, 0>,  cudaFuncAttributeMaxDynamicSharedMemorySize, L_SMEM);
    cudaFuncSetAttribute(gemm_hmma<64, 3, 1>,  cudaFuncAttributeMaxDynamicSharedMemorySize, L_SMEM);
    cudaFuncSetAttribute(gemm_hmma<128, 4, 1>, cudaFuncAttributeMaxDynamicSharedMemorySize, L_SMEM);

    prep_kernel<<<512, 256>>>(W2, D2, W3, D3, W4, D4, W5);  // my idx 0
    knn_kernel<<<dim3(Nc/32, Bc), 1024, KNN_SMEM>>>(x);     // my idx 1

    block1_stats<<<dim3(Nc/2, Bc), 128>>>(x, W1);           // my idx 2
    block1_apply<<<dim3(Nc/2, Bc), 128>>>(x, W1, D1, g1, b1);  // my idx 3 == profiled

    gemm_hmma<64, 2, 0><<<dim3(512, 1), 256, L_SMEM>>>(nullptr, nullptr);
    gemm_hmma<64, 3, 1><<<dim3(512, 1), 256, L_SMEM>>>(g2, b2);
    gemm_hmma<128, 4, 1><<<dim3(512, 2), 256, L_SMEM>>>(g3, b3);
    apply4_kernel<<<(BN*128 + 255)/256, 256>>>(g4, b4);

    conv5_hmma<<<dim3(65536/128, 1024/128), 256, C5_SMEM>>>();
    final_out<<<4, 256>>>(g5, b5, out);
}